// round 1
// baseline (speedup 1.0000x reference)
#include <cuda_runtime.h>
#include <math.h>

// ---------------- problem constants ----------------
constexpr int Bn  = 8;
constexpr int Cn  = 192;
constexpr int Hn  = 224;
constexpr int Wn  = 224;
constexpr int WSz = 7;
constexpr int HW  = Hn * Wn;          // 50176
constexpr int CHW = Cn * HW;          // 9,633,792
constexpr int NH  = Hn / WSz;         // 32
constexpr int NWb = NH * NH;          // 1024 windows per batch image
constexpr int NWIN = Bn * NWb;        // 8192 windows
constexpr int P   = WSz * WSz;        // 49 pixels per window
constexpr int MT  = Bn * HW;          // 401408 pixels total

// ---------------- scratch (device globals; no allocations) ----------------
__device__ float g_q [NWIN * P * Cn];   // [win][pos][chan]
__device__ float g_k [NWIN * P * Cn];
__device__ float g_v [NWIN * P * Cn];
__device__ float g_ow[MT * Cn];         // [pixel-linear m][chan]

// =====================================================================
// K1: fused QKV GEMM.  C[m,n] = sum_k X[m,k] * W[n,k] + b[n]
//   X[m,k] = x[b,k,h,w]  (contiguous in m for fixed k)
//   N = 576 (Wq|Wk|Wv), each 64-wide N-block lies inside one weight.
//   Output scattered to window layout [win][pos][chan].
// =====================================================================
__global__ __launch_bounds__(256) void k_qkv(
    const float* __restrict__ x,
    const float* __restrict__ Wq, const float* __restrict__ bq,
    const float* __restrict__ Wk, const float* __restrict__ bk,
    const float* __restrict__ Wv, const float* __restrict__ bv)
{
    constexpr int BM = 128, BN = 64, BK = 16, BNP = 68;
    __shared__ float As[BK][BM];
    __shared__ float Bs[BK][BNP];

    const int tid = threadIdx.x;
    const int m0  = blockIdx.y * BM;
    const int ng  = blockIdx.x * BN;            // global n in [0,576)
    const int wsel = ng / Cn;
    const int n0   = ng - wsel * Cn;            // n within selected weight

    const float* Wp = (wsel == 0) ? Wq : ((wsel == 1) ? Wk : Wv);
    const float* bp = (wsel == 0) ? bq : ((wsel == 1) ? bk : bv);
    float*       dst = (wsel == 0) ? g_q : ((wsel == 1) ? g_k : g_v);

    // A-tile load plan: 512 float4 slots (16 k x 32 m-quads), 2 per thread.
    int    a_k[2], a_mq[2];
    size_t a_off[2];
#pragma unroll
    for (int it = 0; it < 2; ++it) {
        int s  = tid + it * 256;
        a_k[it]  = s >> 5;
        a_mq[it] = (s & 31) << 2;
        int m   = m0 + a_mq[it];
        int bb  = m / HW;                 // 4-aligned groups never cross batch
        int rem = m - bb * HW;
        a_off[it] = (size_t)bb * CHW + rem;
    }
    // B-tile load plan: 64 n x 4 k-quads, 1 float4 per thread.
    const int bnr = tid >> 2;
    const int bk4 = (tid & 3) << 2;

    const int ty = tid >> 4;   // 16 rows of threads  -> m
    const int tx = tid & 15;   // 16 cols of threads  -> n

    float acc[8][4];
#pragma unroll
    for (int i = 0; i < 8; ++i)
#pragma unroll
        for (int j = 0; j < 4; ++j) acc[i][j] = 0.f;

    // prologue: tile 0 -> smem
    {
        float4 rA0 = *(const float4*)(x + a_off[0] + (size_t)a_k[0] * HW);
        float4 rA1 = *(const float4*)(x + a_off[1] + (size_t)a_k[1] * HW);
        float4 rB  = *(const float4*)(Wp + (size_t)(n0 + bnr) * Cn + bk4);
        *(float4*)(&As[a_k[0]][a_mq[0]]) = rA0;
        *(float4*)(&As[a_k[1]][a_mq[1]]) = rA1;
        Bs[bk4 + 0][bnr] = rB.x; Bs[bk4 + 1][bnr] = rB.y;
        Bs[bk4 + 2][bnr] = rB.z; Bs[bk4 + 3][bnr] = rB.w;
    }
    __syncthreads();

    const int NT = Cn / BK;   // 12
    for (int t = 0; t < NT; ++t) {
        float4 nA0, nA1, nB;
        const int kn = (t + 1) * BK;
        if (t + 1 < NT) {
            nA0 = *(const float4*)(x + a_off[0] + (size_t)(kn + a_k[0]) * HW);
            nA1 = *(const float4*)(x + a_off[1] + (size_t)(kn + a_k[1]) * HW);
            nB  = *(const float4*)(Wp + (size_t)(n0 + bnr) * Cn + kn + bk4);
        }
#pragma unroll
        for (int kk = 0; kk < BK; ++kk) {
            float4 a0 = *(const float4*)(&As[kk][ty * 8]);
            float4 a1 = *(const float4*)(&As[kk][ty * 8 + 4]);
            float4 b  = *(const float4*)(&Bs[kk][tx * 4]);
            float af[8] = {a0.x, a0.y, a0.z, a0.w, a1.x, a1.y, a1.z, a1.w};
            float bf[4] = {b.x, b.y, b.z, b.w};
#pragma unroll
            for (int i = 0; i < 8; ++i)
#pragma unroll
                for (int j = 0; j < 4; ++j)
                    acc[i][j] += af[i] * bf[j];
        }
        __syncthreads();
        if (t + 1 < NT) {
            *(float4*)(&As[a_k[0]][a_mq[0]]) = nA0;
            *(float4*)(&As[a_k[1]][a_mq[1]]) = nA1;
            Bs[bk4 + 0][bnr] = nB.x; Bs[bk4 + 1][bnr] = nB.y;
            Bs[bk4 + 2][bnr] = nB.z; Bs[bk4 + 3][bnr] = nB.w;
            __syncthreads();
        }
    }

    // epilogue: bias + scatter to window layout
    float4 bias;
    bias.x = bp[n0 + tx * 4 + 0];
    bias.y = bp[n0 + tx * 4 + 1];
    bias.z = bp[n0 + tx * 4 + 2];
    bias.w = bp[n0 + tx * 4 + 3];
#pragma unroll
    for (int i = 0; i < 8; ++i) {
        int m   = m0 + ty * 8 + i;
        int bb  = m / HW;
        int rem = m - bb * HW;
        int h   = rem / Wn;
        int w   = rem - h * Wn;
        int hb  = h / WSz, wb = w / WSz;
        int win = bb * NWb + hb * NH + wb;
        int pp  = (h - hb * WSz) * WSz + (w - wb * WSz);
        float4 o;
        o.x = acc[i][0] + bias.x;
        o.y = acc[i][1] + bias.y;
        o.z = acc[i][2] + bias.z;
        o.w = acc[i][3] + bias.w;
        *(float4*)(dst + (size_t)(win * P + pp) * Cn + n0 + tx * 4) = o;
    }
}

// =====================================================================
// K2: per-window attention.  One CTA per window (8192 CTAs, 256 thr).
//   smem: qT/kT transposed [chan][pix] stride 52, v row-major, attnT.
// =====================================================================
constexpr int PS = 52;  // padded pixel stride (mult of 4, breaks conflicts)
constexpr int SMEM_ATTN_BYTES = (2 * Cn * PS + P * Cn + P * PS) * 4; // 127,696

__global__ __launch_bounds__(256) void k_attn()
{
    extern __shared__ float sm[];
    float* qT = sm;                 // [Cn][PS]
    float* kT = qT + Cn * PS;       // [Cn][PS]
    float* vv = kT + Cn * PS;       // [P][Cn]
    float* at = vv + P * Cn;        // attnT: [j][i] stride PS

    const int win = blockIdx.x;
    const int tid = threadIdx.x;
    const float* qg = g_q + (size_t)win * P * Cn;
    const float* kg = g_k + (size_t)win * P * Cn;
    const float* vg = g_v + (size_t)win * P * Cn;

    // load q,k (transpose) and v
    for (int s = tid; s < P * Cn / 4; s += 256) {     // 2352 float4 per tensor
        int p  = s / (Cn / 4);
        int c4 = (s - p * (Cn / 4)) * 4;
        float4 a = *(const float4*)(qg + p * Cn + c4);
        qT[(c4 + 0) * PS + p] = a.x; qT[(c4 + 1) * PS + p] = a.y;
        qT[(c4 + 2) * PS + p] = a.z; qT[(c4 + 3) * PS + p] = a.w;
        float4 b = *(const float4*)(kg + p * Cn + c4);
        kT[(c4 + 0) * PS + p] = b.x; kT[(c4 + 1) * PS + p] = b.y;
        kT[(c4 + 2) * PS + p] = b.z; kT[(c4 + 3) * PS + p] = b.w;
        float4 c = *(const float4*)(vg + p * Cn + c4);
        *(float4*)(vv + p * Cn + c4) = c;
    }
    __syncthreads();

    // Phase A: logits[i][j] = q_i . k_j / sqrt(C); 4x4 tiles over 52x52 grid
    if (tid < 169) {
        int ti = tid % 13, tj = tid / 13;
        int i0 = ti * 4, j0 = tj * 4;
        float acc[4][4];
#pragma unroll
        for (int ii = 0; ii < 4; ++ii)
#pragma unroll
            for (int jj = 0; jj < 4; ++jj) acc[ii][jj] = 0.f;
        for (int kk = 0; kk < Cn; ++kk) {
            float4 a = *(const float4*)(qT + kk * PS + i0);
            float4 b = *(const float4*)(kT + kk * PS + j0);
            float af[4] = {a.x, a.y, a.z, a.w};
            float bf[4] = {b.x, b.y, b.z, b.w};
#pragma unroll
            for (int ii = 0; ii < 4; ++ii)
#pragma unroll
                for (int jj = 0; jj < 4; ++jj)
                    acc[ii][jj] += af[ii] * bf[jj];
        }
        const float sc = 0.07216878364870323f;   // 1/sqrt(192)
#pragma unroll
        for (int ii = 0; ii < 4; ++ii)
#pragma unroll
            for (int jj = 0; jj < 4; ++jj) {
                int i = i0 + ii, j = j0 + jj;
                if (i < P && j < P) at[j * PS + i] = acc[ii][jj] * sc;
            }
    }
    __syncthreads();

    // softmax over j for each row i
    if (tid < P) {
        int i = tid;
        float mx = -1e30f;
        for (int j = 0; j < P; ++j) mx = fmaxf(mx, at[j * PS + i]);
        float ssum = 0.f;
        for (int j = 0; j < P; ++j) {
            float e = __expf(at[j * PS + i] - mx);
            at[j * PS + i] = e;
            ssum += e;
        }
        float r = 1.f / ssum;
        for (int j = 0; j < P; ++j) at[j * PS + i] *= r;
    }
    __syncthreads();

    // Phase B: ow[i][c] = sum_j attn[i][j] * v[j][c]; 4x8 tiles
    const int bb   = win >> 10;        // /NWb
    const int remw = win & 1023;
    const int wh   = remw >> 5, ww = remw & 31;
    for (int t = tid; t < 13 * 24; t += 256) {
        int tc = t % 24, ti2 = t / 24;
        int i0 = ti2 * 4, c0 = tc * 8;
        float acc[4][8];
#pragma unroll
        for (int ii = 0; ii < 4; ++ii)
#pragma unroll
            for (int cc = 0; cc < 8; ++cc) acc[ii][cc] = 0.f;
        for (int j = 0; j < P; ++j) {
            float4 a  = *(const float4*)(at + j * PS + i0);
            float4 v0 = *(const float4*)(vv + j * Cn + c0);
            float4 v1 = *(const float4*)(vv + j * Cn + c0 + 4);
            float af[4] = {a.x, a.y, a.z, a.w};
            float vf[8] = {v0.x, v0.y, v0.z, v0.w, v1.x, v1.y, v1.z, v1.w};
#pragma unroll
            for (int ii = 0; ii < 4; ++ii)
#pragma unroll
                for (int cc = 0; cc < 8; ++cc)
                    acc[ii][cc] += af[ii] * vf[cc];
        }
#pragma unroll
        for (int ii = 0; ii < 4; ++ii) {
            int i = i0 + ii;
            if (i < P) {
                int ph = i / WSz;
                int h  = wh * WSz + ph;
                int w  = ww * WSz + (i - ph * WSz);
                int m  = bb * HW + h * Wn + w;   // pixel-linear
                float4 o0, o1;
                o0.x = acc[ii][0]; o0.y = acc[ii][1]; o0.z = acc[ii][2]; o0.w = acc[ii][3];
                o1.x = acc[ii][4]; o1.y = acc[ii][5]; o1.z = acc[ii][6]; o1.w = acc[ii][7];
                *(float4*)(g_ow + (size_t)m * Cn + c0)     = o0;
                *(float4*)(g_ow + (size_t)m * Cn + c0 + 4) = o1;
            }
        }
    }
}

// =====================================================================
// K3: output projection GEMM + bias.
//   A[m,k] = g_ow[m][k] (row-major), B = Wo[n][k], out in [B,C,H,W].
//   Thread tile: 8 m (tx) x 4 n (ty) -> coalesced float4 stores along m.
// =====================================================================
__global__ __launch_bounds__(256) void k_oproj(
    const float* __restrict__ Wo, const float* __restrict__ bo,
    float* __restrict__ out)
{
    constexpr int BM = 128, BN = 64, BK = 16, ASP = 132, BNP = 68;
    __shared__ float As[BK][ASP];
    __shared__ float Bs[BK][BNP];

    const int tid = threadIdx.x;
    const int m0  = blockIdx.y * BM;
    const int n0  = blockIdx.x * BN;

    // A-tile: 512 float4 slots (128 m x 4 k-quads), 2 per thread (transpose in)
    int a_mi[2], a_kq[2];
#pragma unroll
    for (int it = 0; it < 2; ++it) {
        int s = tid + it * 256;
        a_mi[it] = s >> 2;
        a_kq[it] = (s & 3) << 2;
    }
    const int bnr = tid >> 2;
    const int bk4 = (tid & 3) << 2;

    const int tx = tid & 15;   // m
    const int ty = tid >> 4;   // n

    float acc[8][4];           // [m][n]
#pragma unroll
    for (int i = 0; i < 8; ++i)
#pragma unroll
        for (int j = 0; j < 4; ++j) acc[i][j] = 0.f;

    // prologue
    {
        float4 rA0 = *(const float4*)(g_ow + (size_t)(m0 + a_mi[0]) * Cn + a_kq[0]);
        float4 rA1 = *(const float4*)(g_ow + (size_t)(m0 + a_mi[1]) * Cn + a_kq[1]);
        float4 rB  = *(const float4*)(Wo + (size_t)(n0 + bnr) * Cn + bk4);
        As[a_kq[0] + 0][a_mi[0]] = rA0.x; As[a_kq[0] + 1][a_mi[0]] = rA0.y;
        As[a_kq[0] + 2][a_mi[0]] = rA0.z; As[a_kq[0] + 3][a_mi[0]] = rA0.w;
        As[a_kq[1] + 0][a_mi[1]] = rA1.x; As[a_kq[1] + 1][a_mi[1]] = rA1.y;
        As[a_kq[1] + 2][a_mi[1]] = rA1.z; As[a_kq[1] + 3][a_mi[1]] = rA1.w;
        Bs[bk4 + 0][bnr] = rB.x; Bs[bk4 + 1][bnr] = rB.y;
        Bs[bk4 + 2][bnr] = rB.z; Bs[bk4 + 3][bnr] = rB.w;
    }
    __syncthreads();

    const int NT = Cn / BK;
    for (int t = 0; t < NT; ++t) {
        float4 nA0, nA1, nB;
        const int kn = (t + 1) * BK;
        if (t + 1 < NT) {
            nA0 = *(const float4*)(g_ow + (size_t)(m0 + a_mi[0]) * Cn + kn + a_kq[0]);
            nA1 = *(const float4*)(g_ow + (size_t)(m0 + a_mi[1]) * Cn + kn + a_kq[1]);
            nB  = *(const float4*)(Wo + (size_t)(n0 + bnr) * Cn + kn + bk4);
        }
#pragma unroll
        for (int kk = 0; kk < BK; ++kk) {
            float4 a0 = *(const float4*)(&As[kk][tx * 8]);
            float4 a1 = *(const float4*)(&As[kk][tx * 8 + 4]);
            float4 b  = *(const float4*)(&Bs[kk][ty * 4]);
            float af[8] = {a0.x, a0.y, a0.z, a0.w, a1.x, a1.y, a1.z, a1.w};
            float bf[4] = {b.x, b.y, b.z, b.w};
#pragma unroll
            for (int i = 0; i < 8; ++i)
#pragma unroll
                for (int j = 0; j < 4; ++j)
                    acc[i][j] += af[i] * bf[j];
        }
        __syncthreads();
        if (t + 1 < NT) {
            As[a_kq[0] + 0][a_mi[0]] = nA0.x; As[a_kq[0] + 1][a_mi[0]] = nA0.y;
            As[a_kq[0] + 2][a_mi[0]] = nA0.z; As[a_kq[0] + 3][a_mi[0]] = nA0.w;
            As[a_kq[1] + 0][a_mi[1]] = nA1.x; As[a_kq[1] + 1][a_mi[1]] = nA1.y;
            As[a_kq[1] + 2][a_mi[1]] = nA1.z; As[a_kq[1] + 3][a_mi[1]] = nA1.w;
            Bs[bk4 + 0][bnr] = nB.x; Bs[bk4 + 1][bnr] = nB.y;
            Bs[bk4 + 2][bnr] = nB.z; Bs[bk4 + 3][bnr] = nB.w;
            __syncthreads();
        }
    }

    // epilogue: out[b, n, h, w]; 8 consecutive m per thread (same batch)
    const int m   = m0 + tx * 8;
    const int bb  = m / HW;
    const int rem = m - bb * HW;
    float* obase = out + (size_t)bb * CHW + rem;
#pragma unroll
    for (int j = 0; j < 4; ++j) {
        int n = n0 + ty * 4 + j;
        float bj = bo[n];
        float4 lo, hi;
        lo.x = acc[0][j] + bj; lo.y = acc[1][j] + bj;
        lo.z = acc[2][j] + bj; lo.w = acc[3][j] + bj;
        hi.x = acc[4][j] + bj; hi.y = acc[5][j] + bj;
        hi.z = acc[6][j] + bj; hi.w = acc[7][j] + bj;
        *(float4*)(obase + (size_t)n * HW)     = lo;
        *(float4*)(obase + (size_t)n * HW + 4) = hi;
    }
}

// =====================================================================
extern "C" void kernel_launch(void* const* d_in, const int* in_sizes, int n_in,
                              void* d_out, int out_size)
{
    const float* x  = (const float*)d_in[0];
    const float* Wq = (const float*)d_in[1];
    const float* bq = (const float*)d_in[2];
    const float* Wk = (const float*)d_in[3];
    const float* bk = (const float*)d_in[4];
    const float* Wv = (const float*)d_in[5];
    const float* bv = (const float*)d_in[6];
    const float* Wo = (const float*)d_in[7];
    const float* bo = (const float*)d_in[8];
    float* out = (float*)d_out;

    cudaFuncSetAttribute(k_attn, cudaFuncAttributeMaxDynamicSharedMemorySize,
                         SMEM_ATTN_BYTES);

    dim3 g1(576 / 64, MT / 128);   // (9, 3136)
    k_qkv<<<g1, 256>>>(x, Wq, bq, Wk, bk, Wv, bv);

    k_attn<<<NWIN, 256, SMEM_ATTN_BYTES>>>();

    dim3 g3(Cn / 64, MT / 128);    // (3, 3136)
    k_oproj<<<g3, 256>>>(Wo, bo, out);
}

// round 3
// speedup vs baseline: 2.0394x; 2.0394x over previous
#include <cuda_runtime.h>
#include <cstdint>

// ---------------- problem constants ----------------
constexpr int Bn  = 8;
constexpr int Cn  = 192;
constexpr int Hn  = 224;
constexpr int Wn  = 224;
constexpr int WSz = 7;
constexpr int HW  = Hn * Wn;          // 50176
constexpr int CHW = Cn * HW;
constexpr int NH  = Hn / WSz;         // 32
constexpr int NWb = NH * NH;          // 1024
constexpr int NWIN = Bn * NWb;        // 8192
constexpr int P   = WSz * WSz;        // 49
constexpr int MT  = Bn * HW;          // 401408

// ---------------- scratch ----------------
__device__ float g_q [(size_t)NWIN * P * Cn];
__device__ float g_k [(size_t)NWIN * P * Cn];
__device__ float g_v [(size_t)NWIN * P * Cn];
__device__ float g_ow[(size_t)MT * Cn];

// ---------------- helpers ----------------
__device__ __forceinline__ uint32_t f2tf(float f) {
    uint32_t u;
    asm("cvt.rna.tf32.f32 %0, %1;" : "=r"(u) : "f"(f));
    return u;
}
__device__ __forceinline__ uint32_t sw128(uint32_t o) { return o ^ ((o >> 3) & 0x70); }

#define LDSM4(d0, d1, d2, d3, a) \
    asm volatile("ldmatrix.sync.aligned.m8n8.x4.shared.b16 {%0,%1,%2,%3},[%4];" \
        : "=r"(d0), "=r"(d1), "=r"(d2), "=r"(d3) : "r"(a))

#define MMA_TF32(c, a, b) \
    asm volatile("mma.sync.aligned.m16n8k8.row.col.f32.tf32.tf32.f32 " \
        "{%0,%1,%2,%3},{%4,%5,%6,%7},{%8,%9},{%0,%1,%2,%3};" \
        : "+f"((c)[0]), "+f"((c)[1]), "+f"((c)[2]), "+f"((c)[3]) \
        : "r"((a)[0]), "r"((a)[1]), "r"((a)[2]), "r"((a)[3]), \
          "r"((b)[0]), "r"((b)[1]))

// GEMM smem layout (byte offsets from 128-aligned dyn-smem base)
// A: 2 x 64*32*4  = 2 x 8192
// B: 2 x 192*32*4 = 2 x 24576
constexpr int GOFF_A  = 0;
constexpr int GOFF_B  = 16384;
constexpr int GOFF_BI = 65536;
constexpr int SMEM_GEMM_BYTES = 65536 + 768 + 128;

// =====================================================================
// K1: fused QKV GEMM (tf32 mma.sync).
//   D[m,n] = sum_k x[m,k] W[n,k] + b[n] -> window layout [win][pos][chan]
//   grid (MT/64, 3), block 256.  CTA tile 64x192, warp 32x48.
// =====================================================================
__global__ __launch_bounds__(256) void k_qkv_mma(
    const float* __restrict__ x,
    const float* __restrict__ Wq, const float* __restrict__ bq,
    const float* __restrict__ Wk, const float* __restrict__ bk,
    const float* __restrict__ Wv, const float* __restrict__ bv)
{
    extern __shared__ char smraw[];
    uint32_t sraw = (uint32_t)__cvta_generic_to_shared(smraw);
    const uint32_t s0 = (sraw + 127) & ~127u;
    char* sm = smraw + (s0 - sraw);
    float* sbias = (float*)(sm + GOFF_BI);

    const int tid  = threadIdx.x;
    const int lane = tid & 31, wid = tid >> 5;
    const int wm   = wid >> 2, wn = wid & 3;
    const int m0   = blockIdx.x * 64;
    const int wsel = blockIdx.y;

    const float* Wp  = (wsel == 0) ? Wq : ((wsel == 1) ? Wk : Wv);
    const float* bp  = (wsel == 0) ? bq : ((wsel == 1) ? bk : bv);
    float*       dst = (wsel == 0) ? g_q : ((wsel == 1) ? g_k : g_v);

    const int bb = m0 / HW, rem0 = m0 - bb * HW;   // HW % 64 == 0
    const float* xb = x + (size_t)bb * CHW + rem0;

    if (tid < 192) sbias[tid] = bp[tid];

    const int arow = tid & 63;
    const int akq  = (tid >> 6) << 1;     // this thread's two k-quads
    const int lg   = lane >> 3, lr = lane & 7;

    float acc[2][6][4];
#pragma unroll
    for (int i = 0; i < 2; ++i)
#pragma unroll
        for (int j = 0; j < 6; ++j)
#pragma unroll
            for (int c = 0; c < 4; ++c) acc[i][j][c] = 0.f;

    float  a_st[2][4];
    float4 b_st[6];

    auto stage = [&](int kt) {
#pragma unroll
        for (int q = 0; q < 2; ++q) {
            const float* s = xb + (size_t)(kt * 32 + (akq + q) * 4) * HW + arow;
#pragma unroll
            for (int j = 0; j < 4; ++j) a_st[q][j] = s[(size_t)j * HW];
        }
#pragma unroll
        for (int i = 0; i < 6; ++i) {
            int ss = tid + i * 256;
            int bn = ss >> 3, bf = ss & 7;
            b_st[i] = *(const float4*)(Wp + (size_t)bn * Cn + kt * 32 + bf * 4);
        }
    };
    auto commit = [&](int buf) {
        char* ab = sm + GOFF_A + buf * 8192;
        char* bbuf = sm + GOFF_B + buf * 24576;
#pragma unroll
        for (int q = 0; q < 2; ++q) {
            uint4 u;
            u.x = f2tf(a_st[q][0]); u.y = f2tf(a_st[q][1]);
            u.z = f2tf(a_st[q][2]); u.w = f2tf(a_st[q][3]);
            *(uint4*)(ab + sw128((uint32_t)(arow * 128 + (akq + q) * 16))) = u;
        }
#pragma unroll
        for (int i = 0; i < 6; ++i) {
            int ss = tid + i * 256;
            int bn = ss >> 3, bf = ss & 7;
            uint4 u;
            u.x = f2tf(b_st[i].x); u.y = f2tf(b_st[i].y);
            u.z = f2tf(b_st[i].z); u.w = f2tf(b_st[i].w);
            *(uint4*)(bbuf + sw128((uint32_t)(bn * 128 + bf * 16))) = u;
        }
    };

    stage(0); commit(0);
    __syncthreads();

    for (int kt = 0; kt < 6; ++kt) {
        const int cur = kt & 1;
        if (kt < 5) stage(kt + 1);
        const uint32_t abase = s0 + GOFF_A + cur * 8192;
        const uint32_t bbase = s0 + GOFF_B + cur * 24576;
#pragma unroll
        for (int k8 = 0; k8 < 4; ++k8) {
            uint32_t af[2][4];
#pragma unroll
            for (int mt = 0; mt < 2; ++mt) {
                int row = wm * 32 + mt * 16 + ((lg & 1) << 3) + lr;
                uint32_t ad = abase + sw128((uint32_t)(row * 128 + k8 * 32 + ((lg >> 1) << 4)));
                LDSM4(af[mt][0], af[mt][1], af[mt][2], af[mt][3], ad);
            }
            uint32_t bfr[6][2];
#pragma unroll
            for (int np = 0; np < 3; ++np) {
                int nr = wn * 48 + np * 16 + ((lg >> 1) << 3) + lr;
                uint32_t ad = bbase + sw128((uint32_t)(nr * 128 + k8 * 32 + ((lg & 1) << 4)));
                LDSM4(bfr[2 * np][0], bfr[2 * np][1], bfr[2 * np + 1][0], bfr[2 * np + 1][1], ad);
            }
#pragma unroll
            for (int mt = 0; mt < 2; ++mt)
#pragma unroll
                for (int nt = 0; nt < 6; ++nt)
                    MMA_TF32(acc[mt][nt], af[mt], bfr[nt]);
        }
        __syncthreads();
        if (kt < 5) { commit(cur ^ 1); __syncthreads(); }
    }

    // epilogue: bias + scatter to window layout
    const int col0 = wn * 48 + (lane & 3) * 2;
#pragma unroll
    for (int mt = 0; mt < 2; ++mt)
#pragma unroll
        for (int hf = 0; hf < 2; ++hf) {
            int rem = rem0 + wm * 32 + mt * 16 + hf * 8 + (lane >> 2);
            int h = rem / Wn, w = rem - h * Wn;
            int hb = h / WSz, wb = w / WSz;
            int win = bb * NWb + hb * NH + wb;
            int pp  = (h - hb * WSz) * WSz + (w - wb * WSz);
            float* dp = dst + (size_t)(win * P + pp) * Cn;
#pragma unroll
            for (int nt = 0; nt < 6; ++nt) {
                int c = col0 + nt * 8;
                float2 v;
                v.x = acc[mt][nt][hf * 2 + 0] + sbias[c];
                v.y = acc[mt][nt][hf * 2 + 1] + sbias[c + 1];
                *(float2*)(dp + c) = v;
            }
        }
}

// =====================================================================
// K3: output projection GEMM (tf32 mma.sync).
//   D[m,n] = sum_k g_ow[m,k] Wo[n,k] + bo[n]  -> out[b, n, h, w]
//   grid MT/64, block 256.
// =====================================================================
__global__ __launch_bounds__(256) void k_oproj_mma(
    const float* __restrict__ Wo, const float* __restrict__ bo,
    float* __restrict__ out)
{
    extern __shared__ char smraw[];
    uint32_t sraw = (uint32_t)__cvta_generic_to_shared(smraw);
    const uint32_t s0 = (sraw + 127) & ~127u;
    char* sm = smraw + (s0 - sraw);
    float* sbias = (float*)(sm + GOFF_BI);

    const int tid  = threadIdx.x;
    const int lane = tid & 31, wid = tid >> 5;
    const int wm   = wid >> 2, wn = wid & 3;
    const int m0   = blockIdx.x * 64;
    const int bb   = m0 / HW, rem0 = m0 - bb * HW;

    if (tid < 192) sbias[tid] = bo[tid];

    const int lg = lane >> 3, lr = lane & 7;

    float acc[2][6][4];
#pragma unroll
    for (int i = 0; i < 2; ++i)
#pragma unroll
        for (int j = 0; j < 6; ++j)
#pragma unroll
            for (int c = 0; c < 4; ++c) acc[i][j][c] = 0.f;

    float4 a_st[2];
    float4 b_st[6];

    auto stage = [&](int kt) {
#pragma unroll
        for (int i = 0; i < 2; ++i) {
            int ss = tid + i * 256;
            int r = ss >> 3, kq = ss & 7;
            a_st[i] = *(const float4*)(g_ow + (size_t)(m0 + r) * Cn + kt * 32 + kq * 4);
        }
#pragma unroll
        for (int i = 0; i < 6; ++i) {
            int ss = tid + i * 256;
            int bn = ss >> 3, bf = ss & 7;
            b_st[i] = *(const float4*)(Wo + (size_t)bn * Cn + kt * 32 + bf * 4);
        }
    };
    auto commit = [&](int buf) {
        char* ab = sm + GOFF_A + buf * 8192;
        char* bbuf = sm + GOFF_B + buf * 24576;
#pragma unroll
        for (int i = 0; i < 2; ++i) {
            int ss = tid + i * 256;
            int r = ss >> 3, kq = ss & 7;
            uint4 u;
            u.x = f2tf(a_st[i].x); u.y = f2tf(a_st[i].y);
            u.z = f2tf(a_st[i].z); u.w = f2tf(a_st[i].w);
            *(uint4*)(ab + sw128((uint32_t)(r * 128 + kq * 16))) = u;
        }
#pragma unroll
        for (int i = 0; i < 6; ++i) {
            int ss = tid + i * 256;
            int bn = ss >> 3, bf = ss & 7;
            uint4 u;
            u.x = f2tf(b_st[i].x); u.y = f2tf(b_st[i].y);
            u.z = f2tf(b_st[i].z); u.w = f2tf(b_st[i].w);
            *(uint4*)(bbuf + sw128((uint32_t)(bn * 128 + bf * 16))) = u;
        }
    };

    stage(0); commit(0);
    __syncthreads();

    for (int kt = 0; kt < 6; ++kt) {
        const int cur = kt & 1;
        if (kt < 5) stage(kt + 1);
        const uint32_t abase = s0 + GOFF_A + cur * 8192;
        const uint32_t bbase = s0 + GOFF_B + cur * 24576;
#pragma unroll
        for (int k8 = 0; k8 < 4; ++k8) {
            uint32_t af[2][4];
#pragma unroll
            for (int mt = 0; mt < 2; ++mt) {
                int row = wm * 32 + mt * 16 + ((lg & 1) << 3) + lr;
                uint32_t ad = abase + sw128((uint32_t)(row * 128 + k8 * 32 + ((lg >> 1) << 4)));
                LDSM4(af[mt][0], af[mt][1], af[mt][2], af[mt][3], ad);
            }
            uint32_t bfr[6][2];
#pragma unroll
            for (int np = 0; np < 3; ++np) {
                int nr = wn * 48 + np * 16 + ((lg >> 1) << 3) + lr;
                uint32_t ad = bbase + sw128((uint32_t)(nr * 128 + k8 * 32 + ((lg & 1) << 4)));
                LDSM4(bfr[2 * np][0], bfr[2 * np][1], bfr[2 * np + 1][0], bfr[2 * np + 1][1], ad);
            }
#pragma unroll
            for (int mt = 0; mt < 2; ++mt)
#pragma unroll
                for (int nt = 0; nt < 6; ++nt)
                    MMA_TF32(acc[mt][nt], af[mt], bfr[nt]);
        }
        __syncthreads();
        if (kt < 5) { commit(cur ^ 1); __syncthreads(); }
    }

    // epilogue: out[b, c, h, w]
    const int col0 = wn * 48 + (lane & 3) * 2;
    float* ob = out + (size_t)bb * CHW;
#pragma unroll
    for (int mt = 0; mt < 2; ++mt)
#pragma unroll
        for (int hf = 0; hf < 2; ++hf) {
            int rem = rem0 + wm * 32 + mt * 16 + hf * 8 + (lane >> 2);
#pragma unroll
            for (int nt = 0; nt < 6; ++nt) {
#pragma unroll
                for (int j = 0; j < 2; ++j) {
                    int c = col0 + nt * 8 + j;
                    ob[(size_t)c * HW + rem] = acc[mt][nt][hf * 2 + j] + sbias[c];
                }
            }
        }
}

// =====================================================================
// K2: per-window attention. v aliased into qT region -> 90KB smem,
//     2 CTAs/SM.
// =====================================================================
constexpr int PS = 52;
constexpr int SMEM_ATTN_BYTES = (2 * Cn * PS + P * PS) * 4;   // 90064

__global__ __launch_bounds__(256) void k_attn()
{
    extern __shared__ float smf[];
    float* qT = smf;                 // [Cn][PS]
    float* kT = qT + Cn * PS;        // [Cn][PS]
    float* at = kT + Cn * PS;        // attnT [j][i] stride PS
    float* vv = qT;                  // alias: [P][Cn] after phase A

    const int win = blockIdx.x;
    const int tid = threadIdx.x;
    const float* qg = g_q + (size_t)win * P * Cn;
    const float* kg = g_k + (size_t)win * P * Cn;
    const float* vg = g_v + (size_t)win * P * Cn;

    // load q,k transposed
    for (int s = tid; s < P * Cn / 4; s += 256) {
        int p  = s / (Cn / 4);
        int c4 = (s - p * (Cn / 4)) * 4;
        float4 a = *(const float4*)(qg + p * Cn + c4);
        qT[(c4 + 0) * PS + p] = a.x; qT[(c4 + 1) * PS + p] = a.y;
        qT[(c4 + 2) * PS + p] = a.z; qT[(c4 + 3) * PS + p] = a.w;
        float4 b = *(const float4*)(kg + p * Cn + c4);
        kT[(c4 + 0) * PS + p] = b.x; kT[(c4 + 1) * PS + p] = b.y;
        kT[(c4 + 2) * PS + p] = b.z; kT[(c4 + 3) * PS + p] = b.w;
    }
    __syncthreads();

    // Phase A: logits
    if (tid < 169) {
        int ti = tid % 13, tj = tid / 13;
        int i0 = ti * 4, j0 = tj * 4;
        float acc[4][4];
#pragma unroll
        for (int ii = 0; ii < 4; ++ii)
#pragma unroll
            for (int jj = 0; jj < 4; ++jj) acc[ii][jj] = 0.f;
        for (int kk = 0; kk < Cn; ++kk) {
            float4 a = *(const float4*)(qT + kk * PS + i0);
            float4 b = *(const float4*)(kT + kk * PS + j0);
            float af[4] = {a.x, a.y, a.z, a.w};
            float bf[4] = {b.x, b.y, b.z, b.w};
#pragma unroll
            for (int ii = 0; ii < 4; ++ii)
#pragma unroll
                for (int jj = 0; jj < 4; ++jj)
                    acc[ii][jj] += af[ii] * bf[jj];
        }
        const float sc = 0.07216878364870323f;   // 1/sqrt(192)
#pragma unroll
        for (int ii = 0; ii < 4; ++ii)
#pragma unroll
            for (int jj = 0; jj < 4; ++jj) {
                int i = i0 + ii, j = j0 + jj;
                if (i < P && j < P) at[j * PS + i] = acc[ii][jj] * sc;
            }
    }
    __syncthreads();

    // load v (overwrites qT region) + softmax
    for (int s = tid; s < P * Cn / 4; s += 256) {
        int p  = s / (Cn / 4);
        int c4 = (s - p * (Cn / 4)) * 4;
        float4 c = *(const float4*)(vg + p * Cn + c4);
        *(float4*)(vv + p * Cn + c4) = c;
    }
    if (tid < P) {
        int i = tid;
        float mx = -1e30f;
        for (int j = 0; j < P; ++j) mx = fmaxf(mx, at[j * PS + i]);
        float ssum = 0.f;
        for (int j = 0; j < P; ++j) {
            float e = __expf(at[j * PS + i] - mx);
            at[j * PS + i] = e;
            ssum += e;
        }
        float rr = 1.f / ssum;
        for (int j = 0; j < P; ++j) at[j * PS + i] *= rr;
    }
    __syncthreads();

    // Phase B: ow = attn @ v
    const int bb   = win >> 10;
    const int remw = win & 1023;
    const int wh   = remw >> 5, ww = remw & 31;
    for (int t = tid; t < 13 * 24; t += 256) {
        int tc = t % 24, ti2 = t / 24;
        int i0 = ti2 * 4, c0 = tc * 8;
        float acc[4][8];
#pragma unroll
        for (int ii = 0; ii < 4; ++ii)
#pragma unroll
            for (int cc = 0; cc < 8; ++cc) acc[ii][cc] = 0.f;
        for (int j = 0; j < P; ++j) {
            float4 a  = *(const float4*)(at + j * PS + i0);
            float4 v0 = *(const float4*)(vv + j * Cn + c0);
            float4 v1 = *(const float4*)(vv + j * Cn + c0 + 4);
            float af[4] = {a.x, a.y, a.z, a.w};
            float vf[8] = {v0.x, v0.y, v0.z, v0.w, v1.x, v1.y, v1.z, v1.w};
#pragma unroll
            for (int ii = 0; ii < 4; ++ii)
#pragma unroll
                for (int cc = 0; cc < 8; ++cc)
                    acc[ii][cc] += af[ii] * vf[cc];
        }
#pragma unroll
        for (int ii = 0; ii < 4; ++ii) {
            int i = i0 + ii;
            if (i < P) {
                int ph = i / WSz;
                int h  = wh * WSz + ph;
                int w  = ww * WSz + (i - ph * WSz);
                int m  = bb * HW + h * Wn + w;
                float4 o0, o1;
                o0.x = acc[ii][0]; o0.y = acc[ii][1]; o0.z = acc[ii][2]; o0.w = acc[ii][3];
                o1.x = acc[ii][4]; o1.y = acc[ii][5]; o1.z = acc[ii][6]; o1.w = acc[ii][7];
                *(float4*)(g_ow + (size_t)m * Cn + c0)     = o0;
                *(float4*)(g_ow + (size_t)m * Cn + c0 + 4) = o1;
            }
        }
    }
}

// =====================================================================
extern "C" void kernel_launch(void* const* d_in, const int* in_sizes, int n_in,
                              void* d_out, int out_size)
{
    const float* x  = (const float*)d_in[0];
    const float* Wq = (const float*)d_in[1];
    const float* bq = (const float*)d_in[2];
    const float* Wk = (const float*)d_in[3];
    const float* bk = (const float*)d_in[4];
    const float* Wv = (const float*)d_in[5];
    const float* bv = (const float*)d_in[6];
    const float* Wo = (const float*)d_in[7];
    const float* bo = (const float*)d_in[8];
    float* out = (float*)d_out;

    cudaFuncSetAttribute(k_qkv_mma,   cudaFuncAttributeMaxDynamicSharedMemorySize, SMEM_GEMM_BYTES);
    cudaFuncSetAttribute(k_oproj_mma, cudaFuncAttributeMaxDynamicSharedMemorySize, SMEM_GEMM_BYTES);
    cudaFuncSetAttribute(k_attn,      cudaFuncAttributeMaxDynamicSharedMemorySize, SMEM_ATTN_BYTES);

    dim3 g1(MT / 64, 3);
    k_qkv_mma<<<g1, 256, SMEM_GEMM_BYTES>>>(x, Wq, bq, Wk, bk, Wv, bv);

    k_attn<<<NWIN, 256, SMEM_ATTN_BYTES>>>();

    k_oproj_mma<<<MT / 64, 256, SMEM_GEMM_BYTES>>>(Wo, bo, out);
}

// round 4
// speedup vs baseline: 2.7135x; 1.3305x over previous
#include <cuda_runtime.h>
#include <cstdint>

// ---------------- problem constants ----------------
constexpr int Bn  = 8;
constexpr int Cn  = 192;
constexpr int Hn  = 224;
constexpr int Wn  = 224;
constexpr int WSz = 7;
constexpr int HW  = Hn * Wn;          // 50176
constexpr int CHW = Cn * HW;
constexpr int NH  = Hn / WSz;         // 32
constexpr int NWb = NH * NH;          // 1024
constexpr int NWIN = Bn * NWb;        // 8192
constexpr int P   = WSz * WSz;        // 49
constexpr int MT  = Bn * HW;          // 401408

// ---------------- scratch ----------------
__device__ float g_q [(size_t)NWIN * P * Cn];
__device__ float g_k [(size_t)NWIN * P * Cn];
__device__ float g_v [(size_t)NWIN * P * Cn];
__device__ float g_ow[(size_t)MT * Cn];
__device__ float g_xtf[(size_t)MT * Cn];        // x pre-rounded to tf32
__device__ float g_wtf[4][Cn * Cn];             // weights pre-rounded to tf32

// ---------------- helpers ----------------
__device__ __forceinline__ uint32_t f2tf(float f) {
    uint32_t u;
    asm("cvt.rna.tf32.f32 %0, %1;" : "=r"(u) : "f"(f));
    return u;
}
__device__ __forceinline__ uint32_t sw128(uint32_t o) { return o ^ ((o >> 3) & 0x70); }

#define LDSM4(d0, d1, d2, d3, a) \
    asm volatile("ldmatrix.sync.aligned.m8n8.x4.shared.b16 {%0,%1,%2,%3},[%4];" \
        : "=r"(d0), "=r"(d1), "=r"(d2), "=r"(d3) : "r"(a))

#define MMA_TF32(c, a, b) \
    asm volatile("mma.sync.aligned.m16n8k8.row.col.f32.tf32.tf32.f32 " \
        "{%0,%1,%2,%3},{%4,%5,%6,%7},{%8,%9},{%0,%1,%2,%3};" \
        : "+f"((c)[0]), "+f"((c)[1]), "+f"((c)[2]), "+f"((c)[3]) \
        : "r"((a)[0]), "r"((a)[1]), "r"((a)[2]), "r"((a)[3]), \
          "r"((b)[0]), "r"((b)[1]))

#define CP_ASYNC16(dst, src) \
    asm volatile("cp.async.ca.shared.global [%0],[%1],16;" :: "r"(dst), "l"(src))
#define CP_ASYNC4(dst, src) \
    asm volatile("cp.async.ca.shared.global [%0],[%1],4;" :: "r"(dst), "l"(src))
#define CP_COMMIT()  asm volatile("cp.async.commit_group;" ::: "memory")
#define CP_WAIT1()   asm volatile("cp.async.wait_group 1;" ::: "memory")
#define CP_WAIT0()   asm volatile("cp.async.wait_group 0;" ::: "memory")

// =====================================================================
// prepass: round weights / x to tf32 once
// =====================================================================
__global__ void k_prep_w(const float* __restrict__ Wq, const float* __restrict__ Wk,
                         const float* __restrict__ Wv, const float* __restrict__ Wo)
{
    int idx = blockIdx.x * 256 + threadIdx.x;        // < 4*36864
    int wsel = idx / (Cn * Cn);
    int r    = idx - wsel * (Cn * Cn);
    const float* W = (wsel == 0) ? Wq : (wsel == 1) ? Wk : (wsel == 2) ? Wv : Wo;
    g_wtf[wsel][r] = __uint_as_float(f2tf(W[r]));
}

__global__ void k_prep_x(const float* __restrict__ x)
{
    size_t i = (size_t)(blockIdx.x * 256 + threadIdx.x) * 4;
    float4 v = *(const float4*)(x + i);
    float4 o;
    o.x = __uint_as_float(f2tf(v.x));
    o.y = __uint_as_float(f2tf(v.y));
    o.z = __uint_as_float(f2tf(v.z));
    o.w = __uint_as_float(f2tf(v.w));
    *(float4*)(g_xtf + i) = o;
}

// GEMM smem layout
constexpr int GOFF_A  = 0;          // 2 x 8192
constexpr int GOFF_B  = 16384;      // 2 x 24576
constexpr int GOFF_BI = 65536;
constexpr int SMEM_GEMM_BYTES = 65536 + 768 + 128;

// =====================================================================
// K1: fused QKV GEMM (tf32 mma.sync, cp.async pipeline).
// =====================================================================
__global__ __launch_bounds__(256, 2) void k_qkv_mma(
    const float* __restrict__ bq, const float* __restrict__ bk,
    const float* __restrict__ bv)
{
    extern __shared__ char smraw[];
    uint32_t sraw = (uint32_t)__cvta_generic_to_shared(smraw);
    const uint32_t s0 = (sraw + 127) & ~127u;
    char* sm = smraw + (s0 - sraw);
    float* sbias = (float*)(sm + GOFF_BI);

    const int tid  = threadIdx.x;
    const int lane = tid & 31, wid = tid >> 5;
    const int wm   = wid >> 2, wn = wid & 3;
    const int m0   = blockIdx.x * 64;
    const int wsel = blockIdx.y;

    const float* bp  = (wsel == 0) ? bq : ((wsel == 1) ? bk : bv);
    float*       dst = (wsel == 0) ? g_q : ((wsel == 1) ? g_k : g_v);
    const float* Wt  = g_wtf[wsel];

    const int bb = m0 / HW, rem0 = m0 - bb * HW;
    const float* xb = g_xtf + (size_t)bb * CHW + rem0;

    if (tid < 192) sbias[tid] = bp[tid];

    const int lg = lane >> 3, lr = lane & 7;

    // hoisted ldmatrix offsets
    uint32_t offA[2][4], offB[3][4];
#pragma unroll
    for (int mt = 0; mt < 2; ++mt) {
        int row = wm * 32 + mt * 16 + ((lg & 1) << 3) + lr;
#pragma unroll
        for (int k8 = 0; k8 < 4; ++k8)
            offA[mt][k8] = sw128((uint32_t)(row * 128 + k8 * 32 + ((lg >> 1) << 4)));
    }
#pragma unroll
    for (int np = 0; np < 3; ++np) {
        int nr = wn * 48 + np * 16 + ((lg >> 1) << 3) + lr;
#pragma unroll
        for (int k8 = 0; k8 < 4; ++k8)
            offB[np][k8] = sw128((uint32_t)(nr * 128 + k8 * 32 + ((lg & 1) << 4)));
    }

    float acc[2][6][4] = {};

    auto prefetch = [&](int kt, int buf) {
        uint32_t ab  = s0 + GOFF_A + buf * 8192;
        uint32_t bbf = s0 + GOFF_B + buf * 24576;
        const float* xs = xb + (size_t)(kt * 32) * HW;
#pragma unroll
        for (int e = 0; e < 4; ++e) {
            int k = wid * 4 + e;
            const float* s1 = xs + (size_t)k * HW + lane;
            CP_ASYNC4(ab + sw128((uint32_t)(lane * 128 + k * 4)), s1);
            CP_ASYNC4(ab + sw128((uint32_t)((lane + 32) * 128 + k * 4)), s1 + 32);
        }
        const float* wsrc = Wt + kt * 32;
#pragma unroll
        for (int i = 0; i < 6; ++i) {
            int ss = tid + i * 256;
            int bn = ss >> 3, bf = ss & 7;
            CP_ASYNC16(bbf + sw128((uint32_t)(bn * 128 + bf * 16)),
                       wsrc + (size_t)bn * Cn + bf * 4);
        }
    };

    prefetch(0, 0); CP_COMMIT();
    for (int kt = 0; kt < 6; ++kt) {
        const int cur = kt & 1;
        if (kt < 5) { prefetch(kt + 1, cur ^ 1); CP_COMMIT(); CP_WAIT1(); }
        else        { CP_WAIT0(); }
        __syncthreads();
        const uint32_t abase = s0 + GOFF_A + cur * 8192;
        const uint32_t bbase = s0 + GOFF_B + cur * 24576;
#pragma unroll
        for (int k8 = 0; k8 < 4; ++k8) {
            uint32_t af[2][4];
#pragma unroll
            for (int mt = 0; mt < 2; ++mt)
                LDSM4(af[mt][0], af[mt][1], af[mt][2], af[mt][3], abase + offA[mt][k8]);
            uint32_t bfr[6][2];
#pragma unroll
            for (int np = 0; np < 3; ++np)
                LDSM4(bfr[2 * np][0], bfr[2 * np][1], bfr[2 * np + 1][0], bfr[2 * np + 1][1],
                      bbase + offB[np][k8]);
#pragma unroll
            for (int mt = 0; mt < 2; ++mt)
#pragma unroll
                for (int nt = 0; nt < 6; ++nt)
                    MMA_TF32(acc[mt][nt], af[mt], bfr[nt]);
        }
        __syncthreads();
    }

    // epilogue: bias + tf32 round + scatter to window layout
    const int col0 = wn * 48 + (lane & 3) * 2;
#pragma unroll
    for (int mt = 0; mt < 2; ++mt)
#pragma unroll
        for (int hf = 0; hf < 2; ++hf) {
            int rem = rem0 + wm * 32 + mt * 16 + hf * 8 + (lane >> 2);
            int h = rem / Wn, w = rem - h * Wn;
            int hb = h / WSz, wb = w / WSz;
            int win = bb * NWb + hb * NH + wb;
            int pp  = (h - hb * WSz) * WSz + (w - wb * WSz);
            float* dp = dst + (size_t)(win * P + pp) * Cn;
#pragma unroll
            for (int nt = 0; nt < 6; ++nt) {
                int c = col0 + nt * 8;
                float2 v;
                v.x = __uint_as_float(f2tf(acc[mt][nt][hf * 2 + 0] + sbias[c]));
                v.y = __uint_as_float(f2tf(acc[mt][nt][hf * 2 + 1] + sbias[c + 1]));
                *(float2*)(dp + c) = v;
            }
        }
}

// =====================================================================
// K3: output projection GEMM (tf32 mma.sync, cp.async, no cvt needed —
//     g_ow and g_wtf already tf32).
// =====================================================================
__global__ __launch_bounds__(256, 2) void k_oproj_mma(
    const float* __restrict__ bo, float* __restrict__ out)
{
    extern __shared__ char smraw[];
    uint32_t sraw = (uint32_t)__cvta_generic_to_shared(smraw);
    const uint32_t s0 = (sraw + 127) & ~127u;
    char* sm = smraw + (s0 - sraw);
    float* sbias = (float*)(sm + GOFF_BI);

    const int tid  = threadIdx.x;
    const int lane = tid & 31, wid = tid >> 5;
    const int wm   = wid >> 2, wn = wid & 3;
    const int m0   = blockIdx.x * 64;
    const int bb   = m0 / HW, rem0 = m0 - bb * HW;
    const float* Wt = g_wtf[3];

    if (tid < 192) sbias[tid] = bo[tid];

    const int lg = lane >> 3, lr = lane & 7;

    uint32_t offA[2][4], offB[3][4];
#pragma unroll
    for (int mt = 0; mt < 2; ++mt) {
        int row = wm * 32 + mt * 16 + ((lg & 1) << 3) + lr;
#pragma unroll
        for (int k8 = 0; k8 < 4; ++k8)
            offA[mt][k8] = sw128((uint32_t)(row * 128 + k8 * 32 + ((lg >> 1) << 4)));
    }
#pragma unroll
    for (int np = 0; np < 3; ++np) {
        int nr = wn * 48 + np * 16 + ((lg >> 1) << 3) + lr;
#pragma unroll
        for (int k8 = 0; k8 < 4; ++k8)
            offB[np][k8] = sw128((uint32_t)(nr * 128 + k8 * 32 + ((lg & 1) << 4)));
    }

    float acc[2][6][4] = {};

    auto prefetch = [&](int kt, int buf) {
        uint32_t ab  = s0 + GOFF_A + buf * 8192;
        uint32_t bbf = s0 + GOFF_B + buf * 24576;
#pragma unroll
        for (int i = 0; i < 2; ++i) {
            int ss = tid + i * 256;
            int r = ss >> 3, f = ss & 7;
            CP_ASYNC16(ab + sw128((uint32_t)(r * 128 + f * 16)),
                       g_ow + (size_t)(m0 + r) * Cn + kt * 32 + f * 4);
        }
        const float* wsrc = Wt + kt * 32;
#pragma unroll
        for (int i = 0; i < 6; ++i) {
            int ss = tid + i * 256;
            int bn = ss >> 3, bf = ss & 7;
            CP_ASYNC16(bbf + sw128((uint32_t)(bn * 128 + bf * 16)),
                       wsrc + (size_t)bn * Cn + bf * 4);
        }
    };

    prefetch(0, 0); CP_COMMIT();
    for (int kt = 0; kt < 6; ++kt) {
        const int cur = kt & 1;
        if (kt < 5) { prefetch(kt + 1, cur ^ 1); CP_COMMIT(); CP_WAIT1(); }
        else        { CP_WAIT0(); }
        __syncthreads();
        const uint32_t abase = s0 + GOFF_A + cur * 8192;
        const uint32_t bbase = s0 + GOFF_B + cur * 24576;
#pragma unroll
        for (int k8 = 0; k8 < 4; ++k8) {
            uint32_t af[2][4];
#pragma unroll
            for (int mt = 0; mt < 2; ++mt)
                LDSM4(af[mt][0], af[mt][1], af[mt][2], af[mt][3], abase + offA[mt][k8]);
            uint32_t bfr[6][2];
#pragma unroll
            for (int np = 0; np < 3; ++np)
                LDSM4(bfr[2 * np][0], bfr[2 * np][1], bfr[2 * np + 1][0], bfr[2 * np + 1][1],
                      bbase + offB[np][k8]);
#pragma unroll
            for (int mt = 0; mt < 2; ++mt)
#pragma unroll
                for (int nt = 0; nt < 6; ++nt)
                    MMA_TF32(acc[mt][nt], af[mt], bfr[nt]);
        }
        __syncthreads();
    }

    // epilogue: out[b, c, h, w]
    const int col0 = wn * 48 + (lane & 3) * 2;
    float* ob = out + (size_t)bb * CHW;
#pragma unroll
    for (int mt = 0; mt < 2; ++mt)
#pragma unroll
        for (int hf = 0; hf < 2; ++hf) {
            int rem = rem0 + wm * 32 + mt * 16 + hf * 8 + (lane >> 2);
#pragma unroll
            for (int nt = 0; nt < 6; ++nt) {
#pragma unroll
                for (int j = 0; j < 2; ++j) {
                    int c = col0 + nt * 8 + j;
                    ob[(size_t)c * HW + rem] = acc[mt][nt][hf * 2 + j] + sbias[c];
                }
            }
        }
}

// =====================================================================
// K2: per-window attention on tensor cores (tf32).
//   128 threads (4 warps), one window per CTA.
//   Phase A: S = q k^T / sqrt(C)  (M=64, N=64 padded, K=192 in 6 chunks)
//   softmax fp32, probs stored tf32 (cols 49..55 zeroed)
//   Phase B: O = S v  (K=56 padded, v transposed per 64-chan chunk)
// =====================================================================
constexpr int AOFF_Q = 0;          // 2 x 8192
constexpr int AOFF_K = 16384;      // 2 x 8192
constexpr int AOFF_S = 32768;      // 64 x 68 floats = 17408 B
constexpr int AOFF_VT = 0;         // reuse phase-A buffers
constexpr int SMEM_ATTN_BYTES = 32768 + 17408 + 128;

__global__ __launch_bounds__(128, 4) void k_attn_mma()
{
    extern __shared__ char smraw[];
    uint32_t sraw = (uint32_t)__cvta_generic_to_shared(smraw);
    const uint32_t s0 = (sraw + 127) & ~127u;
    char* sm = smraw + (s0 - sraw);

    const int tid  = threadIdx.x;
    const int lane = tid & 31, wm = tid >> 5;
    const int lg   = lane >> 3, lr = lane & 7;
    const int win  = blockIdx.x;

    const float* qg = g_q + (size_t)win * P * Cn;
    const float* kg = g_k + (size_t)win * P * Cn;
    const float* vg = g_v + (size_t)win * P * Cn;
    float* sS  = (float*)(sm + AOFF_S);
    float* sVT = (float*)(sm + AOFF_VT);

    // hoisted phase-A ldmatrix offsets
    uint32_t offA[4], offB[4][4];
    {
        int row = wm * 16 + ((lg & 1) << 3) + lr;
#pragma unroll
        for (int k8 = 0; k8 < 4; ++k8)
            offA[k8] = sw128((uint32_t)(row * 128 + k8 * 32 + ((lg >> 1) << 4)));
#pragma unroll
        for (int np = 0; np < 4; ++np) {
            int nr = np * 16 + ((lg >> 1) << 3) + lr;
#pragma unroll
            for (int k8 = 0; k8 < 4; ++k8)
                offB[np][k8] = sw128((uint32_t)(nr * 128 + k8 * 32 + ((lg & 1) << 4)));
        }
    }

    auto prefQK = [&](int kt, int buf) {
        uint32_t qb = s0 + AOFF_Q + buf * 8192;
        uint32_t kb = s0 + AOFF_K + buf * 8192;
        for (int s = tid; s < 392; s += 128) {          // 49 rows x 8 quads
            int row = s >> 3, f = s & 7;
            uint32_t o = sw128((uint32_t)(row * 128 + f * 16));
            CP_ASYNC16(qb + o, qg + (size_t)row * Cn + kt * 32 + f * 4);
            CP_ASYNC16(kb + o, kg + (size_t)row * Cn + kt * 32 + f * 4);
        }
    };

    float acc[8][4] = {};
    prefQK(0, 0); CP_COMMIT();
    for (int kt = 0; kt < 6; ++kt) {
        const int cur = kt & 1;
        if (kt < 5) { prefQK(kt + 1, cur ^ 1); CP_COMMIT(); CP_WAIT1(); }
        else        { CP_WAIT0(); }
        __syncthreads();
        const uint32_t qb = s0 + AOFF_Q + cur * 8192;
        const uint32_t kb = s0 + AOFF_K + cur * 8192;
#pragma unroll
        for (int k8 = 0; k8 < 4; ++k8) {
            uint32_t af[4];
            LDSM4(af[0], af[1], af[2], af[3], qb + offA[k8]);
            uint32_t bfr[8][2];
#pragma unroll
            for (int np = 0; np < 4; ++np)
                LDSM4(bfr[2 * np][0], bfr[2 * np][1], bfr[2 * np + 1][0], bfr[2 * np + 1][1],
                      kb + offB[np][k8]);
#pragma unroll
            for (int nt = 0; nt < 8; ++nt)
                MMA_TF32(acc[nt], af, bfr[nt]);
        }
        __syncthreads();
    }

    // write scaled S (fp32) to smem
    const float sc = 0.07216878364870323f;     // 1/sqrt(192)
    {
        int rbase = wm * 16 + (lane >> 2);
        int cb = (lane & 3) * 2;
#pragma unroll
        for (int hf = 0; hf < 2; ++hf) {
            int i = rbase + hf * 8;
#pragma unroll
            for (int nt = 0; nt < 8; ++nt) {
                float2 v;
                v.x = acc[nt][hf * 2 + 0] * sc;
                v.y = acc[nt][hf * 2 + 1] * sc;
                *(float2*)(sS + i * 68 + nt * 8 + cb) = v;
            }
        }
    }
    __syncthreads();

    // softmax (rows 0..48 over cols 0..48); write tf32 probs; zero pad cols
    if (tid < P) {
        float* r = sS + tid * 68;
        float mx = -1e30f;
#pragma unroll 7
        for (int j = 0; j < P; ++j) mx = fmaxf(mx, r[j]);
        float sum = 0.f;
#pragma unroll 7
        for (int j = 0; j < P; ++j) { float e = __expf(r[j] - mx); r[j] = e; sum += e; }
        float inv = 1.f / sum;
#pragma unroll 7
        for (int j = 0; j < P; ++j) r[j] = __uint_as_float(f2tf(r[j] * inv));
#pragma unroll
        for (int j = P; j < 56; ++j) r[j] = 0.f;
    }
    __syncthreads();

    // Phase B: O = S @ V, 3 chunks of 64 channels
    const int bbw = win >> 10, wh = (win >> 5) & 31, ww = win & 31;
    const int rowSA = wm * 16 + ((lg & 1) << 3) + lr;
    const uint32_t aS0 = s0 + AOFF_S + rowSA * 272 + ((lg >> 1) << 4);
    const int nrB = ((lg >> 1) << 3) + lr;
    const uint32_t bV0 = s0 + AOFF_VT + nrB * 272 + ((lg & 1) << 4);

    for (int cc = 0; cc < 3; ++cc) {
        __syncthreads();                    // sVT free (prev readers done)
        const int c0 = cc * 64;
        // transpose-load v chunk: sVT[c][j]
        for (int s = tid; s < 49 * 16; s += 128) {
            int j = s >> 4, cq = s & 15;
            float4 v = *(const float4*)(vg + (size_t)j * Cn + c0 + cq * 4);
            float* d = sVT + (4 * cq) * 68 + j;
            d[0] = v.x; d[68] = v.y; d[136] = v.z; d[204] = v.w;
        }
        // zero pad rows j = 49..55
        for (int s = tid; s < 64 * 7; s += 128) {
            int c = s / 7, j = 49 + s - (s / 7) * 7;
            sVT[c * 68 + j] = 0.f;
        }
        __syncthreads();

        float acc2[8][4] = {};
#pragma unroll
        for (int k8 = 0; k8 < 7; ++k8) {
            uint32_t af[4];
            LDSM4(af[0], af[1], af[2], af[3], aS0 + k8 * 32);
            uint32_t bfr[8][2];
#pragma unroll
            for (int np = 0; np < 4; ++np)
                LDSM4(bfr[2 * np][0], bfr[2 * np][1], bfr[2 * np + 1][0], bfr[2 * np + 1][1],
                      bV0 + np * 16 * 272 + k8 * 32);
#pragma unroll
            for (int nt = 0; nt < 8; ++nt)
                MMA_TF32(acc2[nt], af, bfr[nt]);
        }

        // store O chunk (tf32-rounded) to g_ow pixel-linear
        int rbase = wm * 16 + (lane >> 2);
        int cb = (lane & 3) * 2;
#pragma unroll
        for (int hf = 0; hf < 2; ++hf) {
            int i = rbase + hf * 8;
            if (i < P) {
                int ph = i / WSz, pw = i - ph * WSz;
                int m = bbw * HW + (wh * WSz + ph) * Wn + ww * WSz + pw;
                float* op = g_ow + (size_t)m * Cn + c0 + cb;
#pragma unroll
                for (int nt = 0; nt < 8; ++nt) {
                    float2 v;
                    v.x = __uint_as_float(f2tf(acc2[nt][hf * 2 + 0]));
                    v.y = __uint_as_float(f2tf(acc2[nt][hf * 2 + 1]));
                    *(float2*)(op + nt * 8) = v;
                }
            }
        }
    }
}

// =====================================================================
extern "C" void kernel_launch(void* const* d_in, const int* in_sizes, int n_in,
                              void* d_out, int out_size)
{
    const float* x  = (const float*)d_in[0];
    const float* Wq = (const float*)d_in[1];
    const float* bq = (const float*)d_in[2];
    const float* Wk = (const float*)d_in[3];
    const float* bk = (const float*)d_in[4];
    const float* Wv = (const float*)d_in[5];
    const float* bv = (const float*)d_in[6];
    const float* Wo = (const float*)d_in[7];
    const float* bo = (const float*)d_in[8];
    float* out = (float*)d_out;

    cudaFuncSetAttribute(k_qkv_mma,   cudaFuncAttributeMaxDynamicSharedMemorySize, SMEM_GEMM_BYTES);
    cudaFuncSetAttribute(k_oproj_mma, cudaFuncAttributeMaxDynamicSharedMemorySize, SMEM_GEMM_BYTES);
    cudaFuncSetAttribute(k_attn_mma,  cudaFuncAttributeMaxDynamicSharedMemorySize, SMEM_ATTN_BYTES);

    k_prep_w<<<(4 * Cn * Cn) / 256, 256>>>(Wq, Wk, Wv, Wo);
    k_prep_x<<<(MT * (size_t)Cn) / 4 / 256, 256>>>(x);

    dim3 g1(MT / 64, 3);
    k_qkv_mma<<<g1, 256, SMEM_GEMM_BYTES>>>(bq, bk, bv);

    k_attn_mma<<<NWIN, 128, SMEM_ATTN_BYTES>>>();

    k_oproj_mma<<<MT / 64, 256, SMEM_GEMM_BYTES>>>(bo, out);
}

// round 6
// speedup vs baseline: 2.8401x; 1.0467x over previous
#include <cuda_runtime.h>
#include <cstdint>

// ---------------- problem constants ----------------
constexpr int Bn  = 8;
constexpr int Cn  = 192;
constexpr int Hn  = 224;
constexpr int Wn  = 224;
constexpr int WSz = 7;
constexpr int HW  = Hn * Wn;          // 50176
constexpr int CHW = Cn * HW;
constexpr int NH  = Hn / WSz;         // 32
constexpr int NWb = NH * NH;          // 1024
constexpr int NWIN = Bn * NWb;        // 8192
constexpr int P   = WSz * WSz;        // 49
constexpr int MT  = Bn * HW;          // 401408

// ---------------- scratch ----------------
__device__ float g_q [(size_t)NWIN * P * Cn];
__device__ float g_k [(size_t)NWIN * P * Cn];
__device__ float g_v [(size_t)NWIN * P * Cn];
__device__ float g_ow[(size_t)MT * Cn];
__device__ float g_xtf[(size_t)MT * Cn];        // x pre-rounded to tf32
__device__ float g_wtf[4][Cn * Cn];             // weights pre-rounded to tf32

// ---------------- helpers ----------------
__device__ __forceinline__ uint32_t f2tf(float f) {
    uint32_t u;
    asm("cvt.rna.tf32.f32 %0, %1;" : "=r"(u) : "f"(f));
    return u;
}
__device__ __forceinline__ uint32_t sw128(uint32_t o) { return o ^ ((o >> 3) & 0x70); }

#define LDSM4(d0, d1, d2, d3, a) \
    asm volatile("ldmatrix.sync.aligned.m8n8.x4.shared.b16 {%0,%1,%2,%3},[%4];" \
        : "=r"(d0), "=r"(d1), "=r"(d2), "=r"(d3) : "r"(a))

#define MMA_TF32(c, a, b) \
    asm volatile("mma.sync.aligned.m16n8k8.row.col.f32.tf32.tf32.f32 " \
        "{%0,%1,%2,%3},{%4,%5,%6,%7},{%8,%9},{%0,%1,%2,%3};" \
        : "+f"((c)[0]), "+f"((c)[1]), "+f"((c)[2]), "+f"((c)[3]) \
        : "r"((a)[0]), "r"((a)[1]), "r"((a)[2]), "r"((a)[3]), \
          "r"((b)[0]), "r"((b)[1]))

#define CP_ASYNC16(dst, src) \
    asm volatile("cp.async.ca.shared.global [%0],[%1],16;" :: "r"(dst), "l"(src))
#define CP_ASYNC4(dst, src) \
    asm volatile("cp.async.ca.shared.global [%0],[%1],4;" :: "r"(dst), "l"(src))
#define CP_COMMIT()  asm volatile("cp.async.commit_group;" ::: "memory")
#define CP_WAIT1()   asm volatile("cp.async.wait_group 1;" ::: "memory")
#define CP_WAIT0()   asm volatile("cp.async.wait_group 0;" ::: "memory")

// =====================================================================
// prepass: round weights / x to tf32 once
// =====================================================================
__global__ void k_prep_w(const float* __restrict__ Wq, const float* __restrict__ Wk,
                         const float* __restrict__ Wv, const float* __restrict__ Wo)
{
    int idx = blockIdx.x * 256 + threadIdx.x;
    int wsel = idx / (Cn * Cn);
    int r    = idx - wsel * (Cn * Cn);
    const float* W = (wsel == 0) ? Wq : (wsel == 1) ? Wk : (wsel == 2) ? Wv : Wo;
    g_wtf[wsel][r] = __uint_as_float(f2tf(W[r]));
}

__global__ void k_prep_x(const float* __restrict__ x)
{
    size_t i = (size_t)(blockIdx.x * 256 + threadIdx.x) * 4;
    float4 v = *(const float4*)(x + i);
    float4 o;
    o.x = __uint_as_float(f2tf(v.x));
    o.y = __uint_as_float(f2tf(v.y));
    o.z = __uint_as_float(f2tf(v.z));
    o.w = __uint_as_float(f2tf(v.w));
    *(float4*)(g_xtf + i) = o;
}

// =====================================================================
// K1: single-pass fused QKV GEMM.
//   A tile [64 px][192 k] resident in smem; 3 sequential GEMMs vs Wq/Wk/Wv.
//   grid = MT/64 = 6272, block 256 (8 warps, 2m x 4n).
// =====================================================================
constexpr int Q3_A   = 0;          // 6 chunks x 8192 = 49152
constexpr int Q3_B   = 49152;      // 2 x 24576
constexpr int Q3_BI  = 98304;      // 576 floats
constexpr int SMEM_QKV_BYTES = 98304 + 2304 + 128;

__global__ __launch_bounds__(256, 2) void k_qkv3(
    const float* __restrict__ bq, const float* __restrict__ bk,
    const float* __restrict__ bv)
{
    extern __shared__ char smraw[];
    uint32_t sraw = (uint32_t)__cvta_generic_to_shared(smraw);
    const uint32_t s0 = (sraw + 127) & ~127u;
    char* sm = smraw + (s0 - sraw);
    float* sbias = (float*)(sm + Q3_BI);

    const int tid  = threadIdx.x;
    const int lane = tid & 31, wid = tid >> 5;
    const int wm   = wid >> 2, wn = wid & 3;
    const int m0   = blockIdx.x * 64;
    const int bb   = m0 / HW, rem0 = m0 - bb * HW;
    const float* xb = g_xtf + (size_t)bb * CHW + rem0;

    if (tid < 192) {
        sbias[tid]       = bq[tid];
        sbias[192 + tid] = bk[tid];
        sbias[384 + tid] = bv[tid];
    }

    const int lg = lane >> 3, lr = lane & 7;

    // hoisted ldmatrix offsets (A relative to chunk base)
    uint32_t offA[2][4], offB[3][4];
#pragma unroll
    for (int mt = 0; mt < 2; ++mt) {
        int row = wm * 32 + mt * 16 + ((lg & 1) << 3) + lr;
#pragma unroll
        for (int k8 = 0; k8 < 4; ++k8)
            offA[mt][k8] = sw128((uint32_t)(row * 128 + k8 * 32 + ((lg >> 1) << 4)));
    }
#pragma unroll
    for (int np = 0; np < 3; ++np) {
        int nr = wn * 48 + np * 16 + ((lg >> 1) << 3) + lr;
#pragma unroll
        for (int k8 = 0; k8 < 4; ++k8)
            offB[np][k8] = sw128((uint32_t)(nr * 128 + k8 * 32 + ((lg & 1) << 4)));
    }

    // scatter coords (shared across the 3 outputs)
    int scat[2][2];
#pragma unroll
    for (int mt = 0; mt < 2; ++mt)
#pragma unroll
        for (int hf = 0; hf < 2; ++hf) {
            int rem = rem0 + wm * 32 + mt * 16 + hf * 8 + (lane >> 2);
            int h = rem / Wn, w = rem - h * Wn;
            int hb = h / WSz, wb = w / WSz;
            int win = bb * NWb + hb * NH + wb;
            int pp  = (h - hb * WSz) * WSz + (w - wb * WSz);
            scat[mt][hf] = win * P + pp;
        }

    // ---- issue all A chunk loads (x in [k][px] layout -> 4B cp.async)
#pragma unroll
    for (int c = 0; c < 6; ++c) {
        uint32_t ab = s0 + Q3_A + c * 8192;
        const float* xs = xb + (size_t)(c * 32) * HW;
#pragma unroll
        for (int e = 0; e < 4; ++e) {
            int k = wid * 4 + e;
            const float* s1 = xs + (size_t)k * HW + lane;
            CP_ASYNC4(ab + sw128((uint32_t)(lane * 128 + k * 4)), s1);
            CP_ASYNC4(ab + sw128((uint32_t)((lane + 32) * 128 + k * 4)), s1 + 32);
        }
    }

    auto prefB = [&](int t) {      // t = wsel*6 + kt
        const float* wsrc = g_wtf[t / 6] + (t % 6) * 32;
        uint32_t bbf = s0 + Q3_B + (t & 1) * 24576;
#pragma unroll
        for (int i = 0; i < 6; ++i) {
            int ss = tid + i * 256;
            int bn = ss >> 3, bf = ss & 7;
            CP_ASYNC16(bbf + sw128((uint32_t)(bn * 128 + bf * 16)),
                       wsrc + (size_t)bn * Cn + bf * 4);
        }
    };

    prefB(0); CP_COMMIT();          // G0: A + B(0)
    prefB(1); CP_COMMIT();          // G1: B(1)

    float acc[2][6][4] = {};
    float* dsts[3] = {g_q, g_k, g_v};

    for (int t = 0; t < 18; ++t) {
        if (t < 17) { prefB(t + 1); CP_COMMIT(); CP_WAIT1(); }
        else        { CP_WAIT0(); }
        __syncthreads();
        const int kt = t - (t / 6) * 6;
        const uint32_t abase = s0 + Q3_A + kt * 8192;
        const uint32_t bbase = s0 + Q3_B + (t & 1) * 24576;
#pragma unroll
        for (int k8 = 0; k8 < 4; ++k8) {
            uint32_t af[2][4];
#pragma unroll
            for (int mt = 0; mt < 2; ++mt)
                LDSM4(af[mt][0], af[mt][1], af[mt][2], af[mt][3], abase + offA[mt][k8]);
            uint32_t bfr[6][2];
#pragma unroll
            for (int np = 0; np < 3; ++np)
                LDSM4(bfr[2 * np][0], bfr[2 * np][1], bfr[2 * np + 1][0], bfr[2 * np + 1][1],
                      bbase + offB[np][k8]);
#pragma unroll
            for (int mt = 0; mt < 2; ++mt)
#pragma unroll
                for (int nt = 0; nt < 6; ++nt)
                    MMA_TF32(acc[mt][nt], af[mt], bfr[nt]);
        }
        __syncthreads();

        if (kt == 5) {
            // epilogue for weight w = t/6: bias + tf32 round + window scatter
            const int w = t / 6;
            float* dst = dsts[w];
            const float* bofs = sbias + w * 192;
            const int col0 = wn * 48 + (lane & 3) * 2;
#pragma unroll
            for (int mt = 0; mt < 2; ++mt)
#pragma unroll
                for (int hf = 0; hf < 2; ++hf) {
                    float* dp = dst + (size_t)scat[mt][hf] * Cn;
#pragma unroll
                    for (int nt = 0; nt < 6; ++nt) {
                        int c = col0 + nt * 8;
                        float2 v;
                        v.x = __uint_as_float(f2tf(acc[mt][nt][hf * 2 + 0] + bofs[c]));
                        v.y = __uint_as_float(f2tf(acc[mt][nt][hf * 2 + 1] + bofs[c + 1]));
                        *(float2*)(dp + c) = v;
                        acc[mt][nt][hf * 2 + 0] = 0.f;
                        acc[mt][nt][hf * 2 + 1] = 0.f;
                    }
                }
        }
    }
}

// =====================================================================
// K3: output projection GEMM (unchanged).
// =====================================================================
constexpr int GOFF_A  = 0;
constexpr int GOFF_B  = 16384;
constexpr int GOFF_BI = 65536;
constexpr int SMEM_GEMM_BYTES = 65536 + 768 + 128;

__global__ __launch_bounds__(256, 2) void k_oproj_mma(
    const float* __restrict__ bo, float* __restrict__ out)
{
    extern __shared__ char smraw[];
    uint32_t sraw = (uint32_t)__cvta_generic_to_shared(smraw);
    const uint32_t s0 = (sraw + 127) & ~127u;
    char* sm = smraw + (s0 - sraw);
    float* sbias = (float*)(sm + GOFF_BI);

    const int tid  = threadIdx.x;
    const int lane = tid & 31, wid = tid >> 5;
    const int wm   = wid >> 2, wn = wid & 3;
    const int m0   = blockIdx.x * 64;
    const int bb   = m0 / HW, rem0 = m0 - bb * HW;
    const float* Wt = g_wtf[3];

    if (tid < 192) sbias[tid] = bo[tid];

    const int lg = lane >> 3, lr = lane & 7;

    uint32_t offA[2][4], offB[3][4];
#pragma unroll
    for (int mt = 0; mt < 2; ++mt) {
        int row = wm * 32 + mt * 16 + ((lg & 1) << 3) + lr;
#pragma unroll
        for (int k8 = 0; k8 < 4; ++k8)
            offA[mt][k8] = sw128((uint32_t)(row * 128 + k8 * 32 + ((lg >> 1) << 4)));
    }
#pragma unroll
    for (int np = 0; np < 3; ++np) {
        int nr = wn * 48 + np * 16 + ((lg >> 1) << 3) + lr;
#pragma unroll
        for (int k8 = 0; k8 < 4; ++k8)
            offB[np][k8] = sw128((uint32_t)(nr * 128 + k8 * 32 + ((lg & 1) << 4)));
    }

    float acc[2][6][4] = {};

    auto prefetch = [&](int kt, int buf) {
        uint32_t ab  = s0 + GOFF_A + buf * 8192;
        uint32_t bbf = s0 + GOFF_B + buf * 24576;
#pragma unroll
        for (int i = 0; i < 2; ++i) {
            int ss = tid + i * 256;
            int r = ss >> 3, f = ss & 7;
            CP_ASYNC16(ab + sw128((uint32_t)(r * 128 + f * 16)),
                       g_ow + (size_t)(m0 + r) * Cn + kt * 32 + f * 4);
        }
        const float* wsrc = Wt + kt * 32;
#pragma unroll
        for (int i = 0; i < 6; ++i) {
            int ss = tid + i * 256;
            int bn = ss >> 3, bf = ss & 7;
            CP_ASYNC16(bbf + sw128((uint32_t)(bn * 128 + bf * 16)),
                       wsrc + (size_t)bn * Cn + bf * 4);
        }
    };

    prefetch(0, 0); CP_COMMIT();
    for (int kt = 0; kt < 6; ++kt) {
        const int cur = kt & 1;
        if (kt < 5) { prefetch(kt + 1, cur ^ 1); CP_COMMIT(); CP_WAIT1(); }
        else        { CP_WAIT0(); }
        __syncthreads();
        const uint32_t abase = s0 + GOFF_A + cur * 8192;
        const uint32_t bbase = s0 + GOFF_B + cur * 24576;
#pragma unroll
        for (int k8 = 0; k8 < 4; ++k8) {
            uint32_t af[2][4];
#pragma unroll
            for (int mt = 0; mt < 2; ++mt)
                LDSM4(af[mt][0], af[mt][1], af[mt][2], af[mt][3], abase + offA[mt][k8]);
            uint32_t bfr[6][2];
#pragma unroll
            for (int np = 0; np < 3; ++np)
                LDSM4(bfr[2 * np][0], bfr[2 * np][1], bfr[2 * np + 1][0], bfr[2 * np + 1][1],
                      bbase + offB[np][k8]);
#pragma unroll
            for (int mt = 0; mt < 2; ++mt)
#pragma unroll
                for (int nt = 0; nt < 6; ++nt)
                    MMA_TF32(acc[mt][nt], af[mt], bfr[nt]);
        }
        __syncthreads();
    }

    const int col0 = wn * 48 + (lane & 3) * 2;
    float* ob = out + (size_t)bb * CHW;
#pragma unroll
    for (int mt = 0; mt < 2; ++mt)
#pragma unroll
        for (int hf = 0; hf < 2; ++hf) {
            int rem = rem0 + wm * 32 + mt * 16 + hf * 8 + (lane >> 2);
#pragma unroll
            for (int nt = 0; nt < 6; ++nt) {
#pragma unroll
                for (int j = 0; j < 2; ++j) {
                    int c = col0 + nt * 8 + j;
                    ob[(size_t)c * HW + rem] = acc[mt][nt][hf * 2 + j] + sbias[c];
                }
            }
        }
}

// =====================================================================
// K2: per-window attention (tf32 mma). Packed buffers -> 42.5 KB smem;
//     parallel softmax (2 threads/row) with FULL-warp shfl participation.
// =====================================================================
constexpr int A_QB0 = 0;           // q buf stride 6272, pair stride 12544
constexpr int A_S   = 25088;       // 64 x 68 floats = 17408
constexpr int A_VT  = 0;           // alias over qk bufs after phase A
constexpr int SMEM_ATTN_BYTES = 25088 + 17408 + 128;   // 42624

__global__ __launch_bounds__(128, 4) void k_attn_mma()
{
    extern __shared__ char smraw[];
    uint32_t sraw = (uint32_t)__cvta_generic_to_shared(smraw);
    const uint32_t s0 = (sraw + 127) & ~127u;
    char* sm = smraw + (s0 - sraw);

    const int tid  = threadIdx.x;
    const int lane = tid & 31, wm = tid >> 5;
    const int lg   = lane >> 3, lr = lane & 7;
    const int win  = blockIdx.x;

    const float* qg = g_q + (size_t)win * P * Cn;
    const float* kg = g_k + (size_t)win * P * Cn;
    const float* vg = g_v + (size_t)win * P * Cn;
    float* sS  = (float*)(sm + A_S);
    float* sVT = (float*)(sm + A_VT);

    uint32_t offA[4], offB[4][4];
    {
        int row = wm * 16 + ((lg & 1) << 3) + lr;
#pragma unroll
        for (int k8 = 0; k8 < 4; ++k8)
            offA[k8] = sw128((uint32_t)(row * 128 + k8 * 32 + ((lg >> 1) << 4)));
#pragma unroll
        for (int np = 0; np < 4; ++np) {
            int nr = np * 16 + ((lg >> 1) << 3) + lr;
#pragma unroll
            for (int k8 = 0; k8 < 4; ++k8)
                offB[np][k8] = sw128((uint32_t)(nr * 128 + k8 * 32 + ((lg & 1) << 4)));
        }
    }

    auto prefQK = [&](int kt, int buf) {
        uint32_t qb = s0 + A_QB0 + buf * 12544;
        uint32_t kb = qb + 6272;
        for (int s = tid; s < 392; s += 128) {
            int row = s >> 3, f = s & 7;
            uint32_t o = sw128((uint32_t)(row * 128 + f * 16));
            CP_ASYNC16(qb + o, qg + (size_t)row * Cn + kt * 32 + f * 4);
            CP_ASYNC16(kb + o, kg + (size_t)row * Cn + kt * 32 + f * 4);
        }
    };

    float acc[8][4] = {};
    prefQK(0, 0); CP_COMMIT();
    for (int kt = 0; kt < 6; ++kt) {
        const int cur = kt & 1;
        if (kt < 5) { prefQK(kt + 1, cur ^ 1); CP_COMMIT(); CP_WAIT1(); }
        else        { CP_WAIT0(); }
        __syncthreads();
        const uint32_t qb = s0 + A_QB0 + cur * 12544;
        const uint32_t kb = qb + 6272;
#pragma unroll
        for (int k8 = 0; k8 < 4; ++k8) {
            uint32_t af[4];
            LDSM4(af[0], af[1], af[2], af[3], qb + offA[k8]);
            uint32_t bfr[8][2];
#pragma unroll
            for (int np = 0; np < 4; ++np)
                LDSM4(bfr[2 * np][0], bfr[2 * np][1], bfr[2 * np + 1][0], bfr[2 * np + 1][1],
                      kb + offB[np][k8]);
#pragma unroll
            for (int nt = 0; nt < 8; ++nt)
                MMA_TF32(acc[nt], af, bfr[nt]);
        }
        __syncthreads();
    }

    // write scaled S to smem
    const float sc = 0.07216878364870323f;     // 1/sqrt(192)
    {
        int rbase = wm * 16 + (lane >> 2);
        int cb = (lane & 3) * 2;
#pragma unroll
        for (int hf = 0; hf < 2; ++hf) {
            int i = rbase + hf * 8;
#pragma unroll
            for (int nt = 0; nt < 8; ++nt) {
                float2 v;
                v.x = acc[nt][hf * 2 + 0] * sc;
                v.y = acc[nt][hf * 2 + 1] * sc;
                *(float2*)(sS + i * 68 + nt * 8 + cb) = v;
            }
        }
    }
    __syncthreads();

    // softmax: 2 threads per row; ALL threads run the shfl (no divergence)
    {
        const int row   = tid >> 1, half = tid & 1;
        const bool valid = (row < P);
        float* r = sS + row * 68;
        float mx = -1e30f;
        if (valid)
            for (int j = half; j < P; j += 2) mx = fmaxf(mx, r[j]);
        mx = fmaxf(mx, __shfl_xor_sync(0xFFFFFFFFu, mx, 1));
        float sum = 0.f;
        float ev[25];
        int cnt = 0;
        if (valid)
            for (int j = half; j < P; j += 2) { float e = __expf(r[j] - mx); ev[cnt++] = e; sum += e; }
        sum += __shfl_xor_sync(0xFFFFFFFFu, sum, 1);
        if (valid) {
            float inv = 1.f / sum;
            cnt = 0;
            for (int j = half; j < P; j += 2) r[j] = __uint_as_float(f2tf(ev[cnt++] * inv));
            for (int j = P + half; j < 56; j += 2) r[j] = 0.f;
        }
    }
    __syncthreads();

    // Phase B: O = S @ V, 3 chunks of 64 channels
    const int bbw = win >> 10, wh = (win >> 5) & 31, ww = win & 31;
    const int rowSA = wm * 16 + ((lg & 1) << 3) + lr;
    const uint32_t aS0 = s0 + A_S + rowSA * 272 + ((lg >> 1) << 4);
    const int nrB = ((lg >> 1) << 3) + lr;
    const uint32_t bV0 = s0 + A_VT + nrB * 272 + ((lg & 1) << 4);

    for (int cc = 0; cc < 3; ++cc) {
        __syncthreads();
        const int c0 = cc * 64;
        for (int s = tid; s < 49 * 16; s += 128) {
            int j = s >> 4, cq = s & 15;
            float4 v = *(const float4*)(vg + (size_t)j * Cn + c0 + cq * 4);
            float* d = sVT + (4 * cq) * 68 + j;
            d[0] = v.x; d[68] = v.y; d[136] = v.z; d[204] = v.w;
        }
        for (int s = tid; s < 64 * 7; s += 128) {
            int c = s / 7, j = 49 + s - (s / 7) * 7;
            sVT[c * 68 + j] = 0.f;
        }
        __syncthreads();

        float acc2[8][4] = {};
#pragma unroll
        for (int k8 = 0; k8 < 7; ++k8) {
            uint32_t af[4];
            LDSM4(af[0], af[1], af[2], af[3], aS0 + k8 * 32);
            uint32_t bfr[8][2];
#pragma unroll
            for (int np = 0; np < 4; ++np)
                LDSM4(bfr[2 * np][0], bfr[2 * np][1], bfr[2 * np + 1][0], bfr[2 * np + 1][1],
                      bV0 + np * 16 * 272 + k8 * 32);
#pragma unroll
            for (int nt = 0; nt < 8; ++nt)
                MMA_TF32(acc2[nt], af, bfr[nt]);
        }

        int rbase = wm * 16 + (lane >> 2);
        int cb = (lane & 3) * 2;
#pragma unroll
        for (int hf = 0; hf < 2; ++hf) {
            int i = rbase + hf * 8;
            if (i < P) {
                int ph = i / WSz, pw = i - ph * WSz;
                int m = bbw * HW + (wh * WSz + ph) * Wn + ww * WSz + pw;
                float* op = g_ow + (size_t)m * Cn + c0 + cb;
#pragma unroll
                for (int nt = 0; nt < 8; ++nt) {
                    float2 v;
                    v.x = __uint_as_float(f2tf(acc2[nt][hf * 2 + 0]));
                    v.y = __uint_as_float(f2tf(acc2[nt][hf * 2 + 1]));
                    *(float2*)(op + nt * 8) = v;
                }
            }
        }
    }
}

// =====================================================================
extern "C" void kernel_launch(void* const* d_in, const int* in_sizes, int n_in,
                              void* d_out, int out_size)
{
    const float* x  = (const float*)d_in[0];
    const float* Wq = (const float*)d_in[1];
    const float* bq = (const float*)d_in[2];
    const float* Wk = (const float*)d_in[3];
    const float* bk = (const float*)d_in[4];
    const float* Wv = (const float*)d_in[5];
    const float* bv = (const float*)d_in[6];
    const float* Wo = (const float*)d_in[7];
    const float* bo = (const float*)d_in[8];
    float* out = (float*)d_out;

    cudaFuncSetAttribute(k_qkv3,      cudaFuncAttributeMaxDynamicSharedMemorySize, SMEM_QKV_BYTES);
    cudaFuncSetAttribute(k_oproj_mma, cudaFuncAttributeMaxDynamicSharedMemorySize, SMEM_GEMM_BYTES);
    cudaFuncSetAttribute(k_attn_mma,  cudaFuncAttributeMaxDynamicSharedMemorySize, SMEM_ATTN_BYTES);

    k_prep_w<<<(4 * Cn * Cn) / 256, 256>>>(Wq, Wk, Wv, Wo);
    k_prep_x<<<(MT * (size_t)Cn) / 4 / 256, 256>>>(x);

    k_qkv3<<<MT / 64, 256, SMEM_QKV_BYTES>>>(bq, bk, bv);

    k_attn_mma<<<NWIN, 128, SMEM_ATTN_BYTES>>>();

    k_oproj_mma<<<MT / 64, 256, SMEM_GEMM_BYTES>>>(bo, out);
}

// round 7
// speedup vs baseline: 3.1175x; 1.0976x over previous
#include <cuda_runtime.h>
#include <cstdint>

// ---------------- problem constants ----------------
constexpr int Bn  = 8;
constexpr int Cn  = 192;
constexpr int Hn  = 224;
constexpr int Wn  = 224;
constexpr int WSz = 7;
constexpr int HW  = Hn * Wn;          // 50176
constexpr int CHW = Cn * HW;
constexpr int NH  = Hn / WSz;         // 32
constexpr int NWb = NH * NH;          // 1024
constexpr int NWIN = Bn * NWb;        // 8192
constexpr int P   = WSz * WSz;        // 49
constexpr int MT  = Bn * HW;          // 401408

// ---------------- scratch ----------------
__device__ float g_q [(size_t)NWIN * P * Cn];
__device__ float g_k [(size_t)NWIN * P * Cn];
__device__ float g_v [(size_t)NWIN * P * Cn];
__device__ float g_ow[(size_t)MT * Cn];
__device__ float g_wtf[4][Cn * Cn];             // weights pre-rounded to tf32

// ---------------- helpers ----------------
__device__ __forceinline__ uint32_t f2tf(float f) {
    uint32_t u;
    asm("cvt.rna.tf32.f32 %0, %1;" : "=r"(u) : "f"(f));
    return u;
}
__device__ __forceinline__ uint32_t sw128(uint32_t o) { return o ^ ((o >> 3) & 0x70); }

#define LDSM4(d0, d1, d2, d3, a) \
    asm volatile("ldmatrix.sync.aligned.m8n8.x4.shared.b16 {%0,%1,%2,%3},[%4];" \
        : "=r"(d0), "=r"(d1), "=r"(d2), "=r"(d3) : "r"(a))

#define MMA_TF32(c, a, b) \
    asm volatile("mma.sync.aligned.m16n8k8.row.col.f32.tf32.tf32.f32 " \
        "{%0,%1,%2,%3},{%4,%5,%6,%7},{%8,%9},{%0,%1,%2,%3};" \
        : "+f"((c)[0]), "+f"((c)[1]), "+f"((c)[2]), "+f"((c)[3]) \
        : "r"((a)[0]), "r"((a)[1]), "r"((a)[2]), "r"((a)[3]), \
          "r"((b)[0]), "r"((b)[1]))

#define CP_ASYNC16(dst, src) \
    asm volatile("cp.async.ca.shared.global [%0],[%1],16;" :: "r"(dst), "l"(src))
#define CP_COMMIT()  asm volatile("cp.async.commit_group;" ::: "memory")
#define CP_WAIT1()   asm volatile("cp.async.wait_group 1;" ::: "memory")
#define CP_WAIT0()   asm volatile("cp.async.wait_group 0;" ::: "memory")

// =====================================================================
// prepass: round weights to tf32 once (tiny)
// =====================================================================
__global__ void k_prep_w(const float* __restrict__ Wq, const float* __restrict__ Wk,
                         const float* __restrict__ Wv, const float* __restrict__ Wo)
{
    int idx = blockIdx.x * 256 + threadIdx.x;
    int wsel = idx / (Cn * Cn);
    int r    = idx - wsel * (Cn * Cn);
    const float* W = (wsel == 0) ? Wq : (wsel == 1) ? Wk : (wsel == 2) ? Wv : Wo;
    g_wtf[wsel][r] = __uint_as_float(f2tf(W[r]));
}

// =====================================================================
// K1: single-pass fused QKV GEMM.
//   A tile [64 px][192 k] staged from x (LDG + cvt.rna + STS) and resident;
//   3 sequential GEMMs vs Wq/Wk/Wv (B double-buffered via cp.async).
//   grid = MT/64 = 6272, block 256 (8 warps, 2m x 4n).
// =====================================================================
constexpr int Q3_A   = 0;          // 6 chunks x 8192 = 49152
constexpr int Q3_B   = 49152;      // 2 x 24576
constexpr int Q3_BI  = 98304;      // 576 floats
constexpr int SMEM_QKV_BYTES = 98304 + 2304 + 128;

__global__ __launch_bounds__(256, 2) void k_qkv3(
    const float* __restrict__ x,
    const float* __restrict__ bq, const float* __restrict__ bk,
    const float* __restrict__ bv)
{
    extern __shared__ char smraw[];
    uint32_t sraw = (uint32_t)__cvta_generic_to_shared(smraw);
    const uint32_t s0 = (sraw + 127) & ~127u;
    char* sm = smraw + (s0 - sraw);
    float* sbias = (float*)(sm + Q3_BI);

    const int tid  = threadIdx.x;
    const int lane = tid & 31, wid = tid >> 5;
    const int wm   = wid >> 2, wn = wid & 3;
    const int m0   = blockIdx.x * 64;
    const int bb   = m0 / HW, rem0 = m0 - bb * HW;
    const float* xb = x + (size_t)bb * CHW + rem0;

    if (tid < 192) {
        sbias[tid]       = bq[tid];
        sbias[192 + tid] = bk[tid];
        sbias[384 + tid] = bv[tid];
    }

    const int lg = lane >> 3, lr = lane & 7;

    // hoisted ldmatrix offsets (A relative to chunk base)
    uint32_t offA[2][4], offB[3][4];
#pragma unroll
    for (int mt = 0; mt < 2; ++mt) {
        int row = wm * 32 + mt * 16 + ((lg & 1) << 3) + lr;
#pragma unroll
        for (int k8 = 0; k8 < 4; ++k8)
            offA[mt][k8] = sw128((uint32_t)(row * 128 + k8 * 32 + ((lg >> 1) << 4)));
    }
#pragma unroll
    for (int np = 0; np < 3; ++np) {
        int nr = wn * 48 + np * 16 + ((lg >> 1) << 3) + lr;
#pragma unroll
        for (int k8 = 0; k8 < 4; ++k8)
            offB[np][k8] = sw128((uint32_t)(nr * 128 + k8 * 32 + ((lg & 1) << 4)));
    }

    // scatter coords (shared across the 3 outputs)
    int scat[2][2];
#pragma unroll
    for (int mt = 0; mt < 2; ++mt)
#pragma unroll
        for (int hf = 0; hf < 2; ++hf) {
            int rem = rem0 + wm * 32 + mt * 16 + hf * 8 + (lane >> 2);
            int h = rem / Wn, w = rem - h * Wn;
            int hb = h / WSz, wb = w / WSz;
            int win = bb * NWb + hb * NH + wb;
            int pp  = (h - hb * WSz) * WSz + (w - wb * WSz);
            scat[mt][hf] = win * P + pp;
        }

    // ---- stage all 6 A chunks from x: LDG (coalesced along m) + cvt + STS.128
    {
        const int arow = tid & 63;
        const int akq  = (tid >> 6) << 1;        // 2 k-quads per thread
#pragma unroll
        for (int half = 0; half < 2; ++half) {
            float v[3][8];
#pragma unroll
            for (int c = 0; c < 3; ++c)
#pragma unroll
                for (int q = 0; q < 2; ++q)
#pragma unroll
                    for (int j = 0; j < 4; ++j)
                        v[c][q * 4 + j] =
                            xb[(size_t)((half * 3 + c) * 32 + (akq + q) * 4 + j) * HW + arow];
#pragma unroll
            for (int c = 0; c < 3; ++c) {
                char* ab = sm + Q3_A + (half * 3 + c) * 8192;
#pragma unroll
                for (int q = 0; q < 2; ++q) {
                    uint4 u;
                    u.x = f2tf(v[c][q * 4 + 0]); u.y = f2tf(v[c][q * 4 + 1]);
                    u.z = f2tf(v[c][q * 4 + 2]); u.w = f2tf(v[c][q * 4 + 3]);
                    *(uint4*)(ab + sw128((uint32_t)(arow * 128 + (akq + q) * 16))) = u;
                }
            }
        }
    }

    auto prefB = [&](int t) {      // t = wsel*6 + kt
        const float* wsrc = g_wtf[t / 6] + (t % 6) * 32;
        uint32_t bbf = s0 + Q3_B + (t & 1) * 24576;
#pragma unroll
        for (int i = 0; i < 6; ++i) {
            int ss = tid + i * 256;
            int bn = ss >> 3, bf = ss & 7;
            CP_ASYNC16(bbf + sw128((uint32_t)(bn * 128 + bf * 16)),
                       wsrc + (size_t)bn * Cn + bf * 4);
        }
    };

    prefB(0); CP_COMMIT();
    prefB(1); CP_COMMIT();

    float acc[2][6][4] = {};
    float* dsts[3] = {g_q, g_k, g_v};

    for (int t = 0; t < 18; ++t) {
        if (t < 17) { prefB(t + 1); CP_COMMIT(); CP_WAIT1(); }
        else        { CP_WAIT0(); }
        __syncthreads();
        const int kt = t - (t / 6) * 6;
        const uint32_t abase = s0 + Q3_A + kt * 8192;
        const uint32_t bbase = s0 + Q3_B + (t & 1) * 24576;
#pragma unroll
        for (int k8 = 0; k8 < 4; ++k8) {
            uint32_t af[2][4];
#pragma unroll
            for (int mt = 0; mt < 2; ++mt)
                LDSM4(af[mt][0], af[mt][1], af[mt][2], af[mt][3], abase + offA[mt][k8]);
            uint32_t bfr[6][2];
#pragma unroll
            for (int np = 0; np < 3; ++np)
                LDSM4(bfr[2 * np][0], bfr[2 * np][1], bfr[2 * np + 1][0], bfr[2 * np + 1][1],
                      bbase + offB[np][k8]);
#pragma unroll
            for (int mt = 0; mt < 2; ++mt)
#pragma unroll
                for (int nt = 0; nt < 6; ++nt)
                    MMA_TF32(acc[mt][nt], af[mt], bfr[nt]);
        }
        __syncthreads();

        if (kt == 5) {
            const int w = t / 6;
            float* dst = dsts[w];
            const float* bofs = sbias + w * 192;
            const int col0 = wn * 48 + (lane & 3) * 2;
#pragma unroll
            for (int mt = 0; mt < 2; ++mt)
#pragma unroll
                for (int hf = 0; hf < 2; ++hf) {
                    float* dp = dst + (size_t)scat[mt][hf] * Cn;
#pragma unroll
                    for (int nt = 0; nt < 6; ++nt) {
                        int c = col0 + nt * 8;
                        float2 v;
                        v.x = __uint_as_float(f2tf(acc[mt][nt][hf * 2 + 0] + bofs[c]));
                        v.y = __uint_as_float(f2tf(acc[mt][nt][hf * 2 + 1] + bofs[c + 1]));
                        *(float2*)(dp + c) = v;
                        acc[mt][nt][hf * 2 + 0] = 0.f;
                        acc[mt][nt][hf * 2 + 1] = 0.f;
                    }
                }
        }
    }
}

// =====================================================================
// K3: output projection GEMM (unchanged).
// =====================================================================
constexpr int GOFF_A  = 0;
constexpr int GOFF_B  = 16384;
constexpr int GOFF_BI = 65536;
constexpr int SMEM_GEMM_BYTES = 65536 + 768 + 128;

__global__ __launch_bounds__(256, 2) void k_oproj_mma(
    const float* __restrict__ bo, float* __restrict__ out)
{
    extern __shared__ char smraw[];
    uint32_t sraw = (uint32_t)__cvta_generic_to_shared(smraw);
    const uint32_t s0 = (sraw + 127) & ~127u;
    char* sm = smraw + (s0 - sraw);
    float* sbias = (float*)(sm + GOFF_BI);

    const int tid  = threadIdx.x;
    const int lane = tid & 31, wid = tid >> 5;
    const int wm   = wid >> 2, wn = wid & 3;
    const int m0   = blockIdx.x * 64;
    const int bb   = m0 / HW, rem0 = m0 - bb * HW;
    const float* Wt = g_wtf[3];

    if (tid < 192) sbias[tid] = bo[tid];

    const int lg = lane >> 3, lr = lane & 7;

    uint32_t offA[2][4], offB[3][4];
#pragma unroll
    for (int mt = 0; mt < 2; ++mt) {
        int row = wm * 32 + mt * 16 + ((lg & 1) << 3) + lr;
#pragma unroll
        for (int k8 = 0; k8 < 4; ++k8)
            offA[mt][k8] = sw128((uint32_t)(row * 128 + k8 * 32 + ((lg >> 1) << 4)));
    }
#pragma unroll
    for (int np = 0; np < 3; ++np) {
        int nr = wn * 48 + np * 16 + ((lg >> 1) << 3) + lr;
#pragma unroll
        for (int k8 = 0; k8 < 4; ++k8)
            offB[np][k8] = sw128((uint32_t)(nr * 128 + k8 * 32 + ((lg & 1) << 4)));
    }

    float acc[2][6][4] = {};

    auto prefetch = [&](int kt, int buf) {
        uint32_t ab  = s0 + GOFF_A + buf * 8192;
        uint32_t bbf = s0 + GOFF_B + buf * 24576;
#pragma unroll
        for (int i = 0; i < 2; ++i) {
            int ss = tid + i * 256;
            int r = ss >> 3, f = ss & 7;
            CP_ASYNC16(ab + sw128((uint32_t)(r * 128 + f * 16)),
                       g_ow + (size_t)(m0 + r) * Cn + kt * 32 + f * 4);
        }
        const float* wsrc = Wt + kt * 32;
#pragma unroll
        for (int i = 0; i < 6; ++i) {
            int ss = tid + i * 256;
            int bn = ss >> 3, bf = ss & 7;
            CP_ASYNC16(bbf + sw128((uint32_t)(bn * 128 + bf * 16)),
                       wsrc + (size_t)bn * Cn + bf * 4);
        }
    };

    prefetch(0, 0); CP_COMMIT();
    for (int kt = 0; kt < 6; ++kt) {
        const int cur = kt & 1;
        if (kt < 5) { prefetch(kt + 1, cur ^ 1); CP_COMMIT(); CP_WAIT1(); }
        else        { CP_WAIT0(); }
        __syncthreads();
        const uint32_t abase = s0 + GOFF_A + cur * 8192;
        const uint32_t bbase = s0 + GOFF_B + cur * 24576;
#pragma unroll
        for (int k8 = 0; k8 < 4; ++k8) {
            uint32_t af[2][4];
#pragma unroll
            for (int mt = 0; mt < 2; ++mt)
                LDSM4(af[mt][0], af[mt][1], af[mt][2], af[mt][3], abase + offA[mt][k8]);
            uint32_t bfr[6][2];
#pragma unroll
            for (int np = 0; np < 3; ++np)
                LDSM4(bfr[2 * np][0], bfr[2 * np][1], bfr[2 * np + 1][0], bfr[2 * np + 1][1],
                      bbase + offB[np][k8]);
#pragma unroll
            for (int mt = 0; mt < 2; ++mt)
#pragma unroll
                for (int nt = 0; nt < 6; ++nt)
                    MMA_TF32(acc[mt][nt], af[mt], bfr[nt]);
        }
        __syncthreads();
    }

    const int col0 = wn * 48 + (lane & 3) * 2;
    float* ob = out + (size_t)bb * CHW;
#pragma unroll
    for (int mt = 0; mt < 2; ++mt)
#pragma unroll
        for (int hf = 0; hf < 2; ++hf) {
            int rem = rem0 + wm * 32 + mt * 16 + hf * 8 + (lane >> 2);
#pragma unroll
            for (int nt = 0; nt < 6; ++nt) {
#pragma unroll
                for (int j = 0; j < 2; ++j) {
                    int c = col0 + nt * 8 + j;
                    ob[(size_t)c * HW + rem] = acc[mt][nt][hf * 2 + j] + sbias[c];
                }
            }
        }
}

// =====================================================================
// K2: per-window attention (tf32 mma). 42.5 KB smem; 5 CTAs/SM target;
//     ldmatrix addresses computed inline (reg diet for occupancy).
// =====================================================================
constexpr int A_QB0 = 0;           // q buf stride 6272, pair stride 12544
constexpr int A_S   = 25088;       // 64 x 68 floats = 17408
constexpr int A_VT  = 0;           // alias over qk bufs after phase A
constexpr int SMEM_ATTN_BYTES = 25088 + 17408 + 128;   // 42624

__global__ __launch_bounds__(128, 5) void k_attn_mma()
{
    extern __shared__ char smraw[];
    uint32_t sraw = (uint32_t)__cvta_generic_to_shared(smraw);
    const uint32_t s0 = (sraw + 127) & ~127u;
    char* sm = smraw + (s0 - sraw);

    const int tid  = threadIdx.x;
    const int lane = tid & 31, wm = tid >> 5;
    const int lg   = lane >> 3, lr = lane & 7;
    const int win  = blockIdx.x;

    const float* qg = g_q + (size_t)win * P * Cn;
    const float* kg = g_k + (size_t)win * P * Cn;
    const float* vg = g_v + (size_t)win * P * Cn;
    float* sS  = (float*)(sm + A_S);
    float* sVT = (float*)(sm + A_VT);

    // inline ldmatrix address components (recomputed per use; saves regs)
    const int rowA       = wm * 16 + ((lg & 1) << 3) + lr;
    const uint32_t selA  = (lg >> 1) << 4;
    const uint32_t xorA  = (uint32_t)(rowA & 7) << 4;
    const uint32_t rbA   = (uint32_t)rowA * 128;
    const int nrB0       = ((lg >> 1) << 3) + lr;     // np term added per use
    const uint32_t selB  = (lg & 1) << 4;
    const uint32_t xorB  = (uint32_t)lr << 4;         // (nr&7)==lr for all np

    auto prefQK = [&](int kt, int buf) {
        uint32_t qb = s0 + A_QB0 + buf * 12544;
        uint32_t kb = qb + 6272;
        for (int s = tid; s < 392; s += 128) {
            int row = s >> 3, f = s & 7;
            uint32_t o = sw128((uint32_t)(row * 128 + f * 16));
            CP_ASYNC16(qb + o, qg + (size_t)row * Cn + kt * 32 + f * 4);
            CP_ASYNC16(kb + o, kg + (size_t)row * Cn + kt * 32 + f * 4);
        }
    };

    float acc[8][4] = {};
    prefQK(0, 0); CP_COMMIT();
    for (int kt = 0; kt < 6; ++kt) {
        const int cur = kt & 1;
        if (kt < 5) { prefQK(kt + 1, cur ^ 1); CP_COMMIT(); CP_WAIT1(); }
        else        { CP_WAIT0(); }
        __syncthreads();
        const uint32_t qb = s0 + A_QB0 + cur * 12544;
        const uint32_t kb = qb + 6272;
#pragma unroll
        for (int k8 = 0; k8 < 4; ++k8) {
            uint32_t af[4];
            LDSM4(af[0], af[1], af[2], af[3],
                  qb + rbA + (((uint32_t)(k8 * 32) + selA) ^ xorA));
            uint32_t bfr[8][2];
#pragma unroll
            for (int np = 0; np < 4; ++np) {
                uint32_t nr = (uint32_t)(np * 16 + nrB0);
                LDSM4(bfr[2 * np][0], bfr[2 * np][1], bfr[2 * np + 1][0], bfr[2 * np + 1][1],
                      kb + nr * 128 + (((uint32_t)(k8 * 32) + selB) ^ xorB));
            }
#pragma unroll
            for (int nt = 0; nt < 8; ++nt)
                MMA_TF32(acc[nt], af, bfr[nt]);
        }
        __syncthreads();
    }

    // write scaled S to smem
    const float sc = 0.07216878364870323f;     // 1/sqrt(192)
    {
        int rbase = wm * 16 + (lane >> 2);
        int cb = (lane & 3) * 2;
#pragma unroll
        for (int hf = 0; hf < 2; ++hf) {
            int i = rbase + hf * 8;
#pragma unroll
            for (int nt = 0; nt < 8; ++nt) {
                float2 v;
                v.x = acc[nt][hf * 2 + 0] * sc;
                v.y = acc[nt][hf * 2 + 1] * sc;
                *(float2*)(sS + i * 68 + nt * 8 + cb) = v;
            }
        }
    }
    __syncthreads();

    // softmax: 2 threads per row; ALL threads run the shfl (no divergence)
    {
        const int row   = tid >> 1, half = tid & 1;
        const bool valid = (row < P);
        float* r = sS + row * 68;
        float mx = -1e30f;
        if (valid)
            for (int j = half; j < P; j += 2) mx = fmaxf(mx, r[j]);
        mx = fmaxf(mx, __shfl_xor_sync(0xFFFFFFFFu, mx, 1));
        float sum = 0.f;
        float ev[25];
        int cnt = 0;
        if (valid)
            for (int j = half; j < P; j += 2) { float e = __expf(r[j] - mx); ev[cnt++] = e; sum += e; }
        sum += __shfl_xor_sync(0xFFFFFFFFu, sum, 1);
        if (valid) {
            float inv = 1.f / sum;
            cnt = 0;
            for (int j = half; j < P; j += 2) r[j] = __uint_as_float(f2tf(ev[cnt++] * inv));
            for (int j = P + half; j < 56; j += 2) r[j] = 0.f;
        }
    }
    __syncthreads();

    // Phase B: O = S @ V, 3 chunks of 64 channels
    const int bbw = win >> 10, wh = (win >> 5) & 31, ww = win & 31;
    const uint32_t aS0 = s0 + A_S + (uint32_t)rowA * 272 + selA;   // S rows: 272B stride, no swizzle
    const uint32_t bV0 = s0 + A_VT + (uint32_t)nrB0 * 272 + selB;

    for (int cc = 0; cc < 3; ++cc) {
        __syncthreads();
        const int c0 = cc * 64;
        for (int s = tid; s < 49 * 16; s += 128) {
            int j = s >> 4, cq = s & 15;
            float4 v = *(const float4*)(vg + (size_t)j * Cn + c0 + cq * 4);
            float* d = sVT + (4 * cq) * 68 + j;
            d[0] = v.x; d[68] = v.y; d[136] = v.z; d[204] = v.w;
        }
        for (int s = tid; s < 64 * 7; s += 128) {
            int c = s / 7, j = 49 + s - (s / 7) * 7;
            sVT[c * 68 + j] = 0.f;
        }
        __syncthreads();

        float acc2[8][4] = {};
#pragma unroll
        for (int k8 = 0; k8 < 7; ++k8) {
            uint32_t af[4];
            LDSM4(af[0], af[1], af[2], af[3], aS0 + k8 * 32);
            uint32_t bfr[8][2];
#pragma unroll
            for (int np = 0; np < 4; ++np)
                LDSM4(bfr[2 * np][0], bfr[2 * np][1], bfr[2 * np + 1][0], bfr[2 * np + 1][1],
                      bV0 + np * 16 * 272 + k8 * 32);
#pragma unroll
            for (int nt = 0; nt < 8; ++nt)
                MMA_TF32(acc2[nt], af, bfr[nt]);
        }

        int rbase = wm * 16 + (lane >> 2);
        int cb = (lane & 3) * 2;
#pragma unroll
        for (int hf = 0; hf < 2; ++hf) {
            int i = rbase + hf * 8;
            if (i < P) {
                int ph = i / WSz, pw = i - ph * WSz;
                int m = bbw * HW + (wh * WSz + ph) * Wn + ww * WSz + pw;
                float* op = g_ow + (size_t)m * Cn + c0 + cb;
#pragma unroll
                for (int nt = 0; nt < 8; ++nt) {
                    float2 v;
                    v.x = __uint_as_float(f2tf(acc2[nt][hf * 2 + 0]));
                    v.y = __uint_as_float(f2tf(acc2[nt][hf * 2 + 1]));
                    *(float2*)(op + nt * 8) = v;
                }
            }
        }
    }
}

// =====================================================================
extern "C" void kernel_launch(void* const* d_in, const int* in_sizes, int n_in,
                              void* d_out, int out_size)
{
    const float* x  = (const float*)d_in[0];
    const float* Wq = (const float*)d_in[1];
    const float* bq = (const float*)d_in[2];
    const float* Wk = (const float*)d_in[3];
    const float* bk = (const float*)d_in[4];
    const float* Wv = (const float*)d_in[5];
    const float* bv = (const float*)d_in[6];
    const float* Wo = (const float*)d_in[7];
    const float* bo = (const float*)d_in[8];
    float* out = (float*)d_out;

    cudaFuncSetAttribute(k_qkv3,      cudaFuncAttributeMaxDynamicSharedMemorySize, SMEM_QKV_BYTES);
    cudaFuncSetAttribute(k_oproj_mma, cudaFuncAttributeMaxDynamicSharedMemorySize, SMEM_GEMM_BYTES);
    cudaFuncSetAttribute(k_attn_mma,  cudaFuncAttributeMaxDynamicSharedMemorySize, SMEM_ATTN_BYTES);

    k_prep_w<<<(4 * Cn * Cn) / 256, 256>>>(Wq, Wk, Wv, Wo);

    k_qkv3<<<MT / 64, 256, SMEM_QKV_BYTES>>>(x, bq, bk, bv);

    k_attn_mma<<<NWIN, 128, SMEM_ATTN_BYTES>>>();

    k_oproj_mma<<<MT / 64, 256, SMEM_GEMM_BYTES>>>(bo, out);
}

// round 8
// speedup vs baseline: 3.1515x; 1.0109x over previous
#include <cuda_runtime.h>
#include <cstdint>

// ---------------- problem constants ----------------
constexpr int Bn  = 8;
constexpr int Cn  = 192;
constexpr int Hn  = 224;
constexpr int Wn  = 224;
constexpr int WSz = 7;
constexpr int HW  = Hn * Wn;          // 50176
constexpr int CHW = Cn * HW;
constexpr int NH  = Hn / WSz;         // 32
constexpr int NWb = NH * NH;          // 1024
constexpr int NWIN = Bn * NWb;        // 8192
constexpr int P   = WSz * WSz;        // 49
constexpr int MT  = Bn * HW;          // 401408

// ---------------- scratch ----------------
__device__ float g_q [(size_t)NWIN * P * Cn];
__device__ float g_k [(size_t)NWIN * P * Cn];
__device__ float g_v [(size_t)NWIN * P * Cn];
__device__ float g_ow[(size_t)MT * Cn];
__device__ float g_wtf[4][Cn * Cn];             // weights pre-rounded to tf32

// ---------------- helpers ----------------
__device__ __forceinline__ uint32_t f2tf(float f) {
    uint32_t u;
    asm("cvt.rna.tf32.f32 %0, %1;" : "=r"(u) : "f"(f));
    return u;
}
__device__ __forceinline__ uint32_t sw128(uint32_t o) { return o ^ ((o >> 3) & 0x70); }

#define LDSM4(d0, d1, d2, d3, a) \
    asm volatile("ldmatrix.sync.aligned.m8n8.x4.shared.b16 {%0,%1,%2,%3},[%4];" \
        : "=r"(d0), "=r"(d1), "=r"(d2), "=r"(d3) : "r"(a))

#define MMA_TF32(c, a, b) \
    asm volatile("mma.sync.aligned.m16n8k8.row.col.f32.tf32.tf32.f32 " \
        "{%0,%1,%2,%3},{%4,%5,%6,%7},{%8,%9},{%0,%1,%2,%3};" \
        : "+f"((c)[0]), "+f"((c)[1]), "+f"((c)[2]), "+f"((c)[3]) \
        : "r"((a)[0]), "r"((a)[1]), "r"((a)[2]), "r"((a)[3]), \
          "r"((b)[0]), "r"((b)[1]))

#define CP_ASYNC16(dst, src) \
    asm volatile("cp.async.ca.shared.global [%0],[%1],16;" :: "r"(dst), "l"(src))
#define CP_COMMIT()  asm volatile("cp.async.commit_group;" ::: "memory")
#define CP_WAIT1()   asm volatile("cp.async.wait_group 1;" ::: "memory")
#define CP_WAIT0()   asm volatile("cp.async.wait_group 0;" ::: "memory")

// =====================================================================
// prepass: round weights to tf32 once (tiny)
// =====================================================================
__global__ void k_prep_w(const float* __restrict__ Wq, const float* __restrict__ Wk,
                         const float* __restrict__ Wv, const float* __restrict__ Wo)
{
    int idx = blockIdx.x * 256 + threadIdx.x;
    int wsel = idx / (Cn * Cn);
    int r    = idx - wsel * (Cn * Cn);
    const float* W = (wsel == 0) ? Wq : (wsel == 1) ? Wk : (wsel == 2) ? Wv : Wo;
    g_wtf[wsel][r] = __uint_as_float(f2tf(W[r]));
}

// =====================================================================
// K1: single-pass fused QKV GEMM with PIPELINED A staging.
//   Pass 1 (t=0..5, unrolled): stage chunk t+1 (cvt+STS) and issue LDGs
//   for chunk t+2 while doing chunk t's MMAs. Passes 2-3 reuse A.
//   grid = MT/64 = 6272, block 256 (8 warps, 2m x 4n).
// =====================================================================
constexpr int Q3_A   = 0;          // 6 chunks x 8192 = 49152
constexpr int Q3_B   = 49152;      // 2 x 24576
constexpr int Q3_BI  = 98304;      // 576 floats
constexpr int SMEM_QKV_BYTES = 98304 + 2304 + 128;

__global__ __launch_bounds__(256, 2) void k_qkv3(
    const float* __restrict__ x,
    const float* __restrict__ bq, const float* __restrict__ bk,
    const float* __restrict__ bv)
{
    extern __shared__ char smraw[];
    uint32_t sraw = (uint32_t)__cvta_generic_to_shared(smraw);
    const uint32_t s0 = (sraw + 127) & ~127u;
    char* sm = smraw + (s0 - sraw);
    float* sbias = (float*)(sm + Q3_BI);

    const int tid  = threadIdx.x;
    const int lane = tid & 31, wid = tid >> 5;
    const int wm   = wid >> 2, wn = wid & 3;
    const int m0   = blockIdx.x * 64;
    const int bb   = m0 / HW, rem0 = m0 - bb * HW;
    const float* xb = x + (size_t)bb * CHW + rem0;

    if (tid < 192) {
        sbias[tid]       = bq[tid];
        sbias[192 + tid] = bk[tid];
        sbias[384 + tid] = bv[tid];
    }

    const int lg = lane >> 3, lr = lane & 7;

    // hoisted ldmatrix offsets (A relative to chunk base)
    uint32_t offA[2][4], offB[3][4];
#pragma unroll
    for (int mt = 0; mt < 2; ++mt) {
        int row = wm * 32 + mt * 16 + ((lg & 1) << 3) + lr;
#pragma unroll
        for (int k8 = 0; k8 < 4; ++k8)
            offA[mt][k8] = sw128((uint32_t)(row * 128 + k8 * 32 + ((lg >> 1) << 4)));
    }
#pragma unroll
    for (int np = 0; np < 3; ++np) {
        int nr = wn * 48 + np * 16 + ((lg >> 1) << 3) + lr;
#pragma unroll
        for (int k8 = 0; k8 < 4; ++k8)
            offB[np][k8] = sw128((uint32_t)(nr * 128 + k8 * 32 + ((lg & 1) << 4)));
    }

    // scatter coords (shared across the 3 outputs)
    int scat[2][2];
#pragma unroll
    for (int mt = 0; mt < 2; ++mt)
#pragma unroll
        for (int hf = 0; hf < 2; ++hf) {
            int rem = rem0 + wm * 32 + mt * 16 + hf * 8 + (lane >> 2);
            int h = rem / Wn, w = rem - h * Wn;
            int hb = h / WSz, wb = w / WSz;
            int win = bb * NWb + hb * NH + wb;
            int pp  = (h - hb * WSz) * WSz + (w - wb * WSz);
            scat[mt][hf] = win * P + pp;
        }

    // ---- A staging plumbing: 8 floats/thread/chunk
    const int arow = tid & 63;
    const int akq  = (tid >> 6) << 1;
    float areg[8];

    auto ldA = [&](int c) {
        const float* s = xb + (size_t)(c * 32 + akq * 4) * HW + arow;
#pragma unroll
        for (int j = 0; j < 8; ++j) areg[j] = s[(size_t)j * HW];
    };
    auto stA = [&](int c) {
        char* ab = sm + Q3_A + c * 8192;
        uint4 u0, u1;
        u0.x = f2tf(areg[0]); u0.y = f2tf(areg[1]);
        u0.z = f2tf(areg[2]); u0.w = f2tf(areg[3]);
        u1.x = f2tf(areg[4]); u1.y = f2tf(areg[5]);
        u1.z = f2tf(areg[6]); u1.w = f2tf(areg[7]);
        *(uint4*)(ab + sw128((uint32_t)(arow * 128 + akq * 16)))       = u0;
        *(uint4*)(ab + sw128((uint32_t)(arow * 128 + (akq + 1) * 16))) = u1;
    };

    auto prefB = [&](int t) {      // t = wsel*6 + kt
        const float* wsrc = g_wtf[t / 6] + (t % 6) * 32;
        uint32_t bbf = s0 + Q3_B + (t & 1) * 24576;
#pragma unroll
        for (int i = 0; i < 6; ++i) {
            int ss = tid + i * 256;
            int bn = ss >> 3, bf = ss & 7;
            CP_ASYNC16(bbf + sw128((uint32_t)(bn * 128 + bf * 16)),
                       wsrc + (size_t)bn * Cn + bf * 4);
        }
    };

    float acc[2][6][4] = {};

    auto gemm_step = [&](uint32_t abase, uint32_t bbase) {
#pragma unroll
        for (int k8 = 0; k8 < 4; ++k8) {
            uint32_t af[2][4];
#pragma unroll
            for (int mt = 0; mt < 2; ++mt)
                LDSM4(af[mt][0], af[mt][1], af[mt][2], af[mt][3], abase + offA[mt][k8]);
            uint32_t bfr[6][2];
#pragma unroll
            for (int np = 0; np < 3; ++np)
                LDSM4(bfr[2 * np][0], bfr[2 * np][1], bfr[2 * np + 1][0], bfr[2 * np + 1][1],
                      bbase + offB[np][k8]);
#pragma unroll
            for (int mt = 0; mt < 2; ++mt)
#pragma unroll
                for (int nt = 0; nt < 6; ++nt)
                    MMA_TF32(acc[mt][nt], af[mt], bfr[nt]);
        }
    };

    float* dsts[3] = {g_q, g_k, g_v};
    auto do_epi = [&](int w) {
        float* dst = dsts[w];
        const float* bofs = sbias + w * 192;
        const int col0 = wn * 48 + (lane & 3) * 2;
#pragma unroll
        for (int mt = 0; mt < 2; ++mt)
#pragma unroll
            for (int hf = 0; hf < 2; ++hf) {
                float* dp = dst + (size_t)scat[mt][hf] * Cn;
#pragma unroll
                for (int nt = 0; nt < 6; ++nt) {
                    int c = col0 + nt * 8;
                    float2 v;
                    v.x = __uint_as_float(f2tf(acc[mt][nt][hf * 2 + 0] + bofs[c]));
                    v.y = __uint_as_float(f2tf(acc[mt][nt][hf * 2 + 1] + bofs[c + 1]));
                    *(float2*)(dp + c) = v;
                    acc[mt][nt][hf * 2 + 0] = 0.f;
                    acc[mt][nt][hf * 2 + 1] = 0.f;
                }
            }
    };

    // ---- prologue: chunk 0 staged; chunk 1 LDGs in flight; B(0),B(1) queued
    ldA(0);
    prefB(0); CP_COMMIT();
    prefB(1); CP_COMMIT();
    stA(0);
    ldA(1);
    __syncthreads();               // chunk 0 visible for t=0

    // ---- pass 1 (w=0) with pipelined staging, unrolled
#pragma unroll
    for (int t = 0; t < 6; ++t) {
        prefB(t + 1); CP_COMMIT(); CP_WAIT1();
        if (t > 0) __syncthreads();            // t=0 synced in prologue
        if (t < 5) stA(t + 1);
        if (t < 4) ldA(t + 2);
        gemm_step(s0 + Q3_A + t * 8192, s0 + Q3_B + (t & 1) * 24576);
        __syncthreads();
    }
    do_epi(0);

    // ---- passes 2-3 (w=1,2): A resident, B streamed
    for (int t = 6; t < 18; ++t) {
        if (t < 17) { prefB(t + 1); CP_COMMIT(); CP_WAIT1(); }
        else        { CP_WAIT0(); }
        __syncthreads();
        gemm_step(s0 + Q3_A + (t - (t / 6) * 6) * 8192,
                  s0 + Q3_B + (t & 1) * 24576);
        __syncthreads();
        if (t == 11) do_epi(1);
    }
    do_epi(2);
}

// =====================================================================
// K3: output projection GEMM (unchanged).
// =====================================================================
constexpr int GOFF_A  = 0;
constexpr int GOFF_B  = 16384;
constexpr int GOFF_BI = 65536;
constexpr int SMEM_GEMM_BYTES = 65536 + 768 + 128;

__global__ __launch_bounds__(256, 2) void k_oproj_mma(
    const float* __restrict__ bo, float* __restrict__ out)
{
    extern __shared__ char smraw[];
    uint32_t sraw = (uint32_t)__cvta_generic_to_shared(smraw);
    const uint32_t s0 = (sraw + 127) & ~127u;
    char* sm = smraw + (s0 - sraw);
    float* sbias = (float*)(sm + GOFF_BI);

    const int tid  = threadIdx.x;
    const int lane = tid & 31, wid = tid >> 5;
    const int wm   = wid >> 2, wn = wid & 3;
    const int m0   = blockIdx.x * 64;
    const int bb   = m0 / HW, rem0 = m0 - bb * HW;
    const float* Wt = g_wtf[3];

    if (tid < 192) sbias[tid] = bo[tid];

    const int lg = lane >> 3, lr = lane & 7;

    uint32_t offA[2][4], offB[3][4];
#pragma unroll
    for (int mt = 0; mt < 2; ++mt) {
        int row = wm * 32 + mt * 16 + ((lg & 1) << 3) + lr;
#pragma unroll
        for (int k8 = 0; k8 < 4; ++k8)
            offA[mt][k8] = sw128((uint32_t)(row * 128 + k8 * 32 + ((lg >> 1) << 4)));
    }
#pragma unroll
    for (int np = 0; np < 3; ++np) {
        int nr = wn * 48 + np * 16 + ((lg >> 1) << 3) + lr;
#pragma unroll
        for (int k8 = 0; k8 < 4; ++k8)
            offB[np][k8] = sw128((uint32_t)(nr * 128 + k8 * 32 + ((lg & 1) << 4)));
    }

    float acc[2][6][4] = {};

    auto prefetch = [&](int kt, int buf) {
        uint32_t ab  = s0 + GOFF_A + buf * 8192;
        uint32_t bbf = s0 + GOFF_B + buf * 24576;
#pragma unroll
        for (int i = 0; i < 2; ++i) {
            int ss = tid + i * 256;
            int r = ss >> 3, f = ss & 7;
            CP_ASYNC16(ab + sw128((uint32_t)(r * 128 + f * 16)),
                       g_ow + (size_t)(m0 + r) * Cn + kt * 32 + f * 4);
        }
        const float* wsrc = Wt + kt * 32;
#pragma unroll
        for (int i = 0; i < 6; ++i) {
            int ss = tid + i * 256;
            int bn = ss >> 3, bf = ss & 7;
            CP_ASYNC16(bbf + sw128((uint32_t)(bn * 128 + bf * 16)),
                       wsrc + (size_t)bn * Cn + bf * 4);
        }
    };

    prefetch(0, 0); CP_COMMIT();
    for (int kt = 0; kt < 6; ++kt) {
        const int cur = kt & 1;
        if (kt < 5) { prefetch(kt + 1, cur ^ 1); CP_COMMIT(); CP_WAIT1(); }
        else        { CP_WAIT0(); }
        __syncthreads();
        const uint32_t abase = s0 + GOFF_A + cur * 8192;
        const uint32_t bbase = s0 + GOFF_B + cur * 24576;
#pragma unroll
        for (int k8 = 0; k8 < 4; ++k8) {
            uint32_t af[2][4];
#pragma unroll
            for (int mt = 0; mt < 2; ++mt)
                LDSM4(af[mt][0], af[mt][1], af[mt][2], af[mt][3], abase + offA[mt][k8]);
            uint32_t bfr[6][2];
#pragma unroll
            for (int np = 0; np < 3; ++np)
                LDSM4(bfr[2 * np][0], bfr[2 * np][1], bfr[2 * np + 1][0], bfr[2 * np + 1][1],
                      bbase + offB[np][k8]);
#pragma unroll
            for (int mt = 0; mt < 2; ++mt)
#pragma unroll
                for (int nt = 0; nt < 6; ++nt)
                    MMA_TF32(acc[mt][nt], af[mt], bfr[nt]);
        }
        __syncthreads();
    }

    const int col0 = wn * 48 + (lane & 3) * 2;
    float* ob = out + (size_t)bb * CHW;
#pragma unroll
    for (int mt = 0; mt < 2; ++mt)
#pragma unroll
        for (int hf = 0; hf < 2; ++hf) {
            int rem = rem0 + wm * 32 + mt * 16 + hf * 8 + (lane >> 2);
#pragma unroll
            for (int nt = 0; nt < 6; ++nt) {
#pragma unroll
                for (int j = 0; j < 2; ++j) {
                    int c = col0 + nt * 8 + j;
                    ob[(size_t)c * HW + rem] = acc[mt][nt][hf * 2 + j] + sbias[c];
                }
            }
        }
}

// =====================================================================
// K2: per-window attention (tf32 mma). 42.5 KB smem; 5 CTAs/SM target.
// =====================================================================
constexpr int A_QB0 = 0;           // q buf stride 6272, pair stride 12544
constexpr int A_S   = 25088;       // 64 x 68 floats = 17408
constexpr int A_VT  = 0;           // alias over qk bufs after phase A
constexpr int SMEM_ATTN_BYTES = 25088 + 17408 + 128;   // 42624

__global__ __launch_bounds__(128, 5) void k_attn_mma()
{
    extern __shared__ char smraw[];
    uint32_t sraw = (uint32_t)__cvta_generic_to_shared(smraw);
    const uint32_t s0 = (sraw + 127) & ~127u;
    char* sm = smraw + (s0 - sraw);

    const int tid  = threadIdx.x;
    const int lane = tid & 31, wm = tid >> 5;
    const int lg   = lane >> 3, lr = lane & 7;
    const int win  = blockIdx.x;

    const float* qg = g_q + (size_t)win * P * Cn;
    const float* kg = g_k + (size_t)win * P * Cn;
    const float* vg = g_v + (size_t)win * P * Cn;
    float* sS  = (float*)(sm + A_S);
    float* sVT = (float*)(sm + A_VT);

    // inline ldmatrix address components
    const int rowA       = wm * 16 + ((lg & 1) << 3) + lr;
    const uint32_t selA  = (lg >> 1) << 4;
    const uint32_t xorA  = (uint32_t)(rowA & 7) << 4;
    const uint32_t rbA   = (uint32_t)rowA * 128;
    const int nrB0       = ((lg >> 1) << 3) + lr;
    const uint32_t selB  = (lg & 1) << 4;
    const uint32_t xorB  = (uint32_t)lr << 4;

    auto prefQK = [&](int kt, int buf) {
        uint32_t qb = s0 + A_QB0 + buf * 12544;
        uint32_t kb = qb + 6272;
        for (int s = tid; s < 392; s += 128) {
            int row = s >> 3, f = s & 7;
            uint32_t o = sw128((uint32_t)(row * 128 + f * 16));
            CP_ASYNC16(qb + o, qg + (size_t)row * Cn + kt * 32 + f * 4);
            CP_ASYNC16(kb + o, kg + (size_t)row * Cn + kt * 32 + f * 4);
        }
    };

    float acc[8][4] = {};
    prefQK(0, 0); CP_COMMIT();
    for (int kt = 0; kt < 6; ++kt) {
        const int cur = kt & 1;
        if (kt < 5) { prefQK(kt + 1, cur ^ 1); CP_COMMIT(); CP_WAIT1(); }
        else        { CP_WAIT0(); }
        __syncthreads();
        const uint32_t qb = s0 + A_QB0 + cur * 12544;
        const uint32_t kb = qb + 6272;
#pragma unroll
        for (int k8 = 0; k8 < 4; ++k8) {
            uint32_t af[4];
            LDSM4(af[0], af[1], af[2], af[3],
                  qb + rbA + (((uint32_t)(k8 * 32) + selA) ^ xorA));
            uint32_t bfr[8][2];
#pragma unroll
            for (int np = 0; np < 4; ++np) {
                uint32_t nr = (uint32_t)(np * 16 + nrB0);
                LDSM4(bfr[2 * np][0], bfr[2 * np][1], bfr[2 * np + 1][0], bfr[2 * np + 1][1],
                      kb + nr * 128 + (((uint32_t)(k8 * 32) + selB) ^ xorB));
            }
#pragma unroll
            for (int nt = 0; nt < 8; ++nt)
                MMA_TF32(acc[nt], af, bfr[nt]);
        }
        __syncthreads();
    }

    // write scaled S to smem
    const float sc = 0.07216878364870323f;     // 1/sqrt(192)
    {
        int rbase = wm * 16 + (lane >> 2);
        int cb = (lane & 3) * 2;
#pragma unroll
        for (int hf = 0; hf < 2; ++hf) {
            int i = rbase + hf * 8;
#pragma unroll
            for (int nt = 0; nt < 8; ++nt) {
                float2 v;
                v.x = acc[nt][hf * 2 + 0] * sc;
                v.y = acc[nt][hf * 2 + 1] * sc;
                *(float2*)(sS + i * 68 + nt * 8 + cb) = v;
            }
        }
    }
    __syncthreads();

    // softmax: 2 threads per row; ALL threads run the shfl
    {
        const int row   = tid >> 1, half = tid & 1;
        const bool valid = (row < P);
        float* r = sS + row * 68;
        float mx = -1e30f;
        if (valid)
            for (int j = half; j < P; j += 2) mx = fmaxf(mx, r[j]);
        mx = fmaxf(mx, __shfl_xor_sync(0xFFFFFFFFu, mx, 1));
        float sum = 0.f;
        float ev[25];
        int cnt = 0;
        if (valid)
            for (int j = half; j < P; j += 2) { float e = __expf(r[j] - mx); ev[cnt++] = e; sum += e; }
        sum += __shfl_xor_sync(0xFFFFFFFFu, sum, 1);
        if (valid) {
            float inv = 1.f / sum;
            cnt = 0;
            for (int j = half; j < P; j += 2) r[j] = __uint_as_float(f2tf(ev[cnt++] * inv));
            for (int j = P + half; j < 56; j += 2) r[j] = 0.f;
        }
    }

    // zero sVT pad rows ONCE (region free after phase A; visible after
    // the first chunk's trailing __syncthreads below)
    for (int s = tid; s < 64 * 7; s += 128) {
        int c = s / 7, j = 49 + s - (s / 7) * 7;
        sVT[c * 68 + j] = 0.f;
    }
    __syncthreads();

    // Phase B: O = S @ V, 3 chunks of 64 channels
    const int bbw = win >> 10, wh = (win >> 5) & 31, ww = win & 31;
    const uint32_t aS0 = s0 + A_S + (uint32_t)rowA * 272 + selA;
    const uint32_t bV0 = s0 + A_VT + (uint32_t)nrB0 * 272 + selB;

    for (int cc = 0; cc < 3; ++cc) {
        if (cc > 0) __syncthreads();           // prev chunk readers done
        const int c0 = cc * 64;
        for (int s = tid; s < 49 * 16; s += 128) {
            int j = s >> 4, cq = s & 15;
            float4 v = *(const float4*)(vg + (size_t)j * Cn + c0 + cq * 4);
            float* d = sVT + (4 * cq) * 68 + j;
            d[0] = v.x; d[68] = v.y; d[136] = v.z; d[204] = v.w;
        }
        __syncthreads();

        float acc2[8][4] = {};
#pragma unroll
        for (int k8 = 0; k8 < 7; ++k8) {
            uint32_t af[4];
            LDSM4(af[0], af[1], af[2], af[3], aS0 + k8 * 32);
            uint32_t bfr[8][2];
#pragma unroll
            for (int np = 0; np < 4; ++np)
                LDSM4(bfr[2 * np][0], bfr[2 * np][1], bfr[2 * np + 1][0], bfr[2 * np + 1][1],
                      bV0 + np * 16 * 272 + k8 * 32);
#pragma unroll
            for (int nt = 0; nt < 8; ++nt)
                MMA_TF32(acc2[nt], af, bfr[nt]);
        }

        int rbase = wm * 16 + (lane >> 2);
        int cb = (lane & 3) * 2;
#pragma unroll
        for (int hf = 0; hf < 2; ++hf) {
            int i = rbase + hf * 8;
            if (i < P) {
                int ph = i / WSz, pw = i - ph * WSz;
                int m = bbw * HW + (wh * WSz + ph) * Wn + ww * WSz + pw;
                float* op = g_ow + (size_t)m * Cn + c0 + cb;
#pragma unroll
                for (int nt = 0; nt < 8; ++nt) {
                    float2 v;
                    v.x = __uint_as_float(f2tf(acc2[nt][hf * 2 + 0]));
                    v.y = __uint_as_float(f2tf(acc2[nt][hf * 2 + 1]));
                    *(float2*)(op + nt * 8) = v;
                }
            }
        }
    }
}

// =====================================================================
extern "C" void kernel_launch(void* const* d_in, const int* in_sizes, int n_in,
                              void* d_out, int out_size)
{
    const float* x  = (const float*)d_in[0];
    const float* Wq = (const float*)d_in[1];
    const float* bq = (const float*)d_in[2];
    const float* Wk = (const float*)d_in[3];
    const float* bk = (const float*)d_in[4];
    const float* Wv = (const float*)d_in[5];
    const float* bv = (const float*)d_in[6];
    const float* Wo = (const float*)d_in[7];
    const float* bo = (const float*)d_in[8];
    float* out = (float*)d_out;

    cudaFuncSetAttribute(k_qkv3,      cudaFuncAttributeMaxDynamicSharedMemorySize, SMEM_QKV_BYTES);
    cudaFuncSetAttribute(k_oproj_mma, cudaFuncAttributeMaxDynamicSharedMemorySize, SMEM_GEMM_BYTES);
    cudaFuncSetAttribute(k_attn_mma,  cudaFuncAttributeMaxDynamicSharedMemorySize, SMEM_ATTN_BYTES);

    k_prep_w<<<(4 * Cn * Cn) / 256, 256>>>(Wq, Wk, Wv, Wo);

    k_qkv3<<<MT / 64, 256, SMEM_QKV_BYTES>>>(x, bq, bk, bv);

    k_attn_mma<<<NWIN, 128, SMEM_ATTN_BYTES>>>();

    k_oproj_mma<<<MT / 64, 256, SMEM_GEMM_BYTES>>>(bo, out);
}

// round 10
// speedup vs baseline: 3.5493x; 1.1262x over previous
#include <cuda_runtime.h>
#include <cuda_fp16.h>
#include <cstdint>

// ---------------- problem constants ----------------
constexpr int Bn  = 8;
constexpr int Cn  = 192;
constexpr int Hn  = 224;
constexpr int Wn  = 224;
constexpr int WSz = 7;
constexpr int HW  = Hn * Wn;          // 50176
constexpr int CHW = Cn * HW;
constexpr int NH  = Hn / WSz;         // 32
constexpr int NWb = NH * NH;          // 1024
constexpr int NWIN = Bn * NWb;        // 8192
constexpr int P   = WSz * WSz;        // 49
constexpr int MT  = Bn * HW;          // 401408

// ---------------- scratch ----------------
__device__ __half g_q [(size_t)NWIN * P * Cn];
__device__ __half g_k [(size_t)NWIN * P * Cn];
__device__ __half g_v [(size_t)NWIN * P * Cn];
__device__ float  g_ow[(size_t)MT * Cn];
__device__ float  g_wtf[4][Cn * Cn];            // weights pre-rounded to tf32

// ---------------- helpers ----------------
__device__ __forceinline__ uint32_t f2tf(float f) {
    uint32_t u;
    asm("cvt.rna.tf32.f32 %0, %1;" : "=r"(u) : "f"(f));
    return u;
}
__device__ __forceinline__ uint32_t sw128(uint32_t o) { return o ^ ((o >> 3) & 0x70); }

#define LDSM4(d0, d1, d2, d3, a) \
    asm volatile("ldmatrix.sync.aligned.m8n8.x4.shared.b16 {%0,%1,%2,%3},[%4];" \
        : "=r"(d0), "=r"(d1), "=r"(d2), "=r"(d3) : "r"(a))

#define MMA_TF32(c, a, b) \
    asm volatile("mma.sync.aligned.m16n8k8.row.col.f32.tf32.tf32.f32 " \
        "{%0,%1,%2,%3},{%4,%5,%6,%7},{%8,%9},{%0,%1,%2,%3};" \
        : "+f"((c)[0]), "+f"((c)[1]), "+f"((c)[2]), "+f"((c)[3]) \
        : "r"((a)[0]), "r"((a)[1]), "r"((a)[2]), "r"((a)[3]), \
          "r"((b)[0]), "r"((b)[1]))

#define MMA_F16(c, a, b) \
    asm volatile("mma.sync.aligned.m16n8k16.row.col.f32.f16.f16.f32 " \
        "{%0,%1,%2,%3},{%4,%5,%6,%7},{%8,%9},{%0,%1,%2,%3};" \
        : "+f"((c)[0]), "+f"((c)[1]), "+f"((c)[2]), "+f"((c)[3]) \
        : "r"((a)[0]), "r"((a)[1]), "r"((a)[2]), "r"((a)[3]), \
          "r"((b)[0]), "r"((b)[1]))

#define CP_ASYNC16(dst, src) \
    asm volatile("cp.async.ca.shared.global [%0],[%1],16;" :: "r"(dst), "l"(src))
#define CP_COMMIT()  asm volatile("cp.async.commit_group;" ::: "memory")
#define CP_WAIT1()   asm volatile("cp.async.wait_group 1;" ::: "memory")
#define CP_WAIT0()   asm volatile("cp.async.wait_group 0;" ::: "memory")

// =====================================================================
// prepass: round weights to tf32 once (tiny)
// =====================================================================
__global__ void k_prep_w(const float* __restrict__ Wq, const float* __restrict__ Wk,
                         const float* __restrict__ Wv, const float* __restrict__ Wo)
{
    int idx = blockIdx.x * 256 + threadIdx.x;
    int wsel = idx / (Cn * Cn);
    int r    = idx - wsel * (Cn * Cn);
    const float* W = (wsel == 0) ? Wq : (wsel == 1) ? Wk : (wsel == 2) ? Wv : Wo;
    g_wtf[wsel][r] = __uint_as_float(f2tf(W[r]));
}

// =====================================================================
// K1: single-pass fused QKV GEMM (round-8 structure; epilogue -> fp16).
// =====================================================================
constexpr int Q3_A   = 0;
constexpr int Q3_B   = 49152;
constexpr int Q3_BI  = 98304;
constexpr int SMEM_QKV_BYTES = 98304 + 2304 + 128;

__global__ __launch_bounds__(256, 2) void k_qkv3(
    const float* __restrict__ x,
    const float* __restrict__ bq, const float* __restrict__ bk,
    const float* __restrict__ bv)
{
    extern __shared__ char smraw[];
    uint32_t sraw = (uint32_t)__cvta_generic_to_shared(smraw);
    const uint32_t s0 = (sraw + 127) & ~127u;
    char* sm = smraw + (s0 - sraw);
    float* sbias = (float*)(sm + Q3_BI);

    const int tid  = threadIdx.x;
    const int lane = tid & 31, wid = tid >> 5;
    const int wm   = wid >> 2, wn = wid & 3;
    const int m0   = blockIdx.x * 64;
    const int bb   = m0 / HW, rem0 = m0 - bb * HW;
    const float* xb = x + (size_t)bb * CHW + rem0;

    if (tid < 192) {
        sbias[tid]       = bq[tid];
        sbias[192 + tid] = bk[tid];
        sbias[384 + tid] = bv[tid];
    }

    const int lg = lane >> 3, lr = lane & 7;

    uint32_t offA[2][4], offB[3][4];
#pragma unroll
    for (int mt = 0; mt < 2; ++mt) {
        int row = wm * 32 + mt * 16 + ((lg & 1) << 3) + lr;
#pragma unroll
        for (int k8 = 0; k8 < 4; ++k8)
            offA[mt][k8] = sw128((uint32_t)(row * 128 + k8 * 32 + ((lg >> 1) << 4)));
    }
#pragma unroll
    for (int np = 0; np < 3; ++np) {
        int nr = wn * 48 + np * 16 + ((lg >> 1) << 3) + lr;
#pragma unroll
        for (int k8 = 0; k8 < 4; ++k8)
            offB[np][k8] = sw128((uint32_t)(nr * 128 + k8 * 32 + ((lg & 1) << 4)));
    }

    int scat[2][2];
#pragma unroll
    for (int mt = 0; mt < 2; ++mt)
#pragma unroll
        for (int hf = 0; hf < 2; ++hf) {
            int rem = rem0 + wm * 32 + mt * 16 + hf * 8 + (lane >> 2);
            int h = rem / Wn, w = rem - h * Wn;
            int hb = h / WSz, wb = w / WSz;
            int win = bb * NWb + hb * NH + wb;
            int pp  = (h - hb * WSz) * WSz + (w - wb * WSz);
            scat[mt][hf] = win * P + pp;
        }

    const int arow = tid & 63;
    const int akq  = (tid >> 6) << 1;
    float areg[8];

    auto ldA = [&](int c) {
        const float* s = xb + (size_t)(c * 32 + akq * 4) * HW + arow;
#pragma unroll
        for (int j = 0; j < 8; ++j) areg[j] = s[(size_t)j * HW];
    };
    auto stA = [&](int c) {
        char* ab = sm + Q3_A + c * 8192;
        uint4 u0, u1;
        u0.x = f2tf(areg[0]); u0.y = f2tf(areg[1]);
        u0.z = f2tf(areg[2]); u0.w = f2tf(areg[3]);
        u1.x = f2tf(areg[4]); u1.y = f2tf(areg[5]);
        u1.z = f2tf(areg[6]); u1.w = f2tf(areg[7]);
        *(uint4*)(ab + sw128((uint32_t)(arow * 128 + akq * 16)))       = u0;
        *(uint4*)(ab + sw128((uint32_t)(arow * 128 + (akq + 1) * 16))) = u1;
    };

    auto prefB = [&](int t) {
        const float* wsrc = g_wtf[t / 6] + (t % 6) * 32;
        uint32_t bbf = s0 + Q3_B + (t & 1) * 24576;
#pragma unroll
        for (int i = 0; i < 6; ++i) {
            int ss = tid + i * 256;
            int bn = ss >> 3, bf = ss & 7;
            CP_ASYNC16(bbf + sw128((uint32_t)(bn * 128 + bf * 16)),
                       wsrc + (size_t)bn * Cn + bf * 4);
        }
    };

    float acc[2][6][4] = {};

    auto gemm_step = [&](uint32_t abase, uint32_t bbase) {
#pragma unroll
        for (int k8 = 0; k8 < 4; ++k8) {
            uint32_t af[2][4];
#pragma unroll
            for (int mt = 0; mt < 2; ++mt)
                LDSM4(af[mt][0], af[mt][1], af[mt][2], af[mt][3], abase + offA[mt][k8]);
            uint32_t bfr[6][2];
#pragma unroll
            for (int np = 0; np < 3; ++np)
                LDSM4(bfr[2 * np][0], bfr[2 * np][1], bfr[2 * np + 1][0], bfr[2 * np + 1][1],
                      bbase + offB[np][k8]);
#pragma unroll
            for (int mt = 0; mt < 2; ++mt)
#pragma unroll
                for (int nt = 0; nt < 6; ++nt)
                    MMA_TF32(acc[mt][nt], af[mt], bfr[nt]);
        }
    };

    __half* dsts[3] = {g_q, g_k, g_v};
    auto do_epi = [&](int w) {
        __half* dst = dsts[w];
        const float* bofs = sbias + w * 192;
        const int col0 = wn * 48 + (lane & 3) * 2;
#pragma unroll
        for (int mt = 0; mt < 2; ++mt)
#pragma unroll
            for (int hf = 0; hf < 2; ++hf) {
                __half* dp = dst + (size_t)scat[mt][hf] * Cn;
#pragma unroll
                for (int nt = 0; nt < 6; ++nt) {
                    int c = col0 + nt * 8;
                    *(__half2*)(dp + c) = __floats2half2_rn(
                        acc[mt][nt][hf * 2 + 0] + bofs[c],
                        acc[mt][nt][hf * 2 + 1] + bofs[c + 1]);
                    acc[mt][nt][hf * 2 + 0] = 0.f;
                    acc[mt][nt][hf * 2 + 1] = 0.f;
                }
            }
    };

    ldA(0);
    prefB(0); CP_COMMIT();
    prefB(1); CP_COMMIT();
    stA(0);
    ldA(1);
    __syncthreads();

#pragma unroll
    for (int t = 0; t < 6; ++t) {
        prefB(t + 1); CP_COMMIT(); CP_WAIT1();
        if (t > 0) __syncthreads();
        if (t < 5) stA(t + 1);
        if (t < 4) ldA(t + 2);
        gemm_step(s0 + Q3_A + t * 8192, s0 + Q3_B + (t & 1) * 24576);
        __syncthreads();
    }
    do_epi(0);

    for (int t = 6; t < 18; ++t) {
        if (t < 17) { prefB(t + 1); CP_COMMIT(); CP_WAIT1(); }
        else        { CP_WAIT0(); }
        __syncthreads();
        gemm_step(s0 + Q3_A + (t - (t / 6) * 6) * 8192,
                  s0 + Q3_B + (t & 1) * 24576);
        __syncthreads();
        if (t == 11) do_epi(1);
    }
    do_epi(2);
}

// =====================================================================
// K3: output projection GEMM (unchanged from round 8).
// =====================================================================
constexpr int GOFF_A  = 0;
constexpr int GOFF_B  = 16384;
constexpr int GOFF_BI = 65536;
constexpr int SMEM_GEMM_BYTES = 65536 + 768 + 128;

__global__ __launch_bounds__(256, 2) void k_oproj_mma(
    const float* __restrict__ bo, float* __restrict__ out)
{
    extern __shared__ char smraw[];
    uint32_t sraw = (uint32_t)__cvta_generic_to_shared(smraw);
    const uint32_t s0 = (sraw + 127) & ~127u;
    char* sm = smraw + (s0 - sraw);
    float* sbias = (float*)(sm + GOFF_BI);

    const int tid  = threadIdx.x;
    const int lane = tid & 31, wid = tid >> 5;
    const int wm   = wid >> 2, wn = wid & 3;
    const int m0   = blockIdx.x * 64;
    const int bb   = m0 / HW, rem0 = m0 - bb * HW;
    const float* Wt = g_wtf[3];

    if (tid < 192) sbias[tid] = bo[tid];

    const int lg = lane >> 3, lr = lane & 7;

    uint32_t offA[2][4], offB[3][4];
#pragma unroll
    for (int mt = 0; mt < 2; ++mt) {
        int row = wm * 32 + mt * 16 + ((lg & 1) << 3) + lr;
#pragma unroll
        for (int k8 = 0; k8 < 4; ++k8)
            offA[mt][k8] = sw128((uint32_t)(row * 128 + k8 * 32 + ((lg >> 1) << 4)));
    }
#pragma unroll
    for (int np = 0; np < 3; ++np) {
        int nr = wn * 48 + np * 16 + ((lg >> 1) << 3) + lr;
#pragma unroll
        for (int k8 = 0; k8 < 4; ++k8)
            offB[np][k8] = sw128((uint32_t)(nr * 128 + k8 * 32 + ((lg & 1) << 4)));
    }

    float acc[2][6][4] = {};

    auto prefetch = [&](int kt, int buf) {
        uint32_t ab  = s0 + GOFF_A + buf * 8192;
        uint32_t bbf = s0 + GOFF_B + buf * 24576;
#pragma unroll
        for (int i = 0; i < 2; ++i) {
            int ss = tid + i * 256;
            int r = ss >> 3, f = ss & 7;
            CP_ASYNC16(ab + sw128((uint32_t)(r * 128 + f * 16)),
                       g_ow + (size_t)(m0 + r) * Cn + kt * 32 + f * 4);
        }
        const float* wsrc = Wt + kt * 32;
#pragma unroll
        for (int i = 0; i < 6; ++i) {
            int ss = tid + i * 256;
            int bn = ss >> 3, bf = ss & 7;
            CP_ASYNC16(bbf + sw128((uint32_t)(bn * 128 + bf * 16)),
                       wsrc + (size_t)bn * Cn + bf * 4);
        }
    };

    prefetch(0, 0); CP_COMMIT();
    for (int kt = 0; kt < 6; ++kt) {
        const int cur = kt & 1;
        if (kt < 5) { prefetch(kt + 1, cur ^ 1); CP_COMMIT(); CP_WAIT1(); }
        else        { CP_WAIT0(); }
        __syncthreads();
        const uint32_t abase = s0 + GOFF_A + cur * 8192;
        const uint32_t bbase = s0 + GOFF_B + cur * 24576;
#pragma unroll
        for (int k8 = 0; k8 < 4; ++k8) {
            uint32_t af[2][4];
#pragma unroll
            for (int mt = 0; mt < 2; ++mt)
                LDSM4(af[mt][0], af[mt][1], af[mt][2], af[mt][3], abase + offA[mt][k8]);
            uint32_t bfr[6][2];
#pragma unroll
            for (int np = 0; np < 3; ++np)
                LDSM4(bfr[2 * np][0], bfr[2 * np][1], bfr[2 * np + 1][0], bfr[2 * np + 1][1],
                      bbase + offB[np][k8]);
#pragma unroll
            for (int mt = 0; mt < 2; ++mt)
#pragma unroll
                for (int nt = 0; nt < 6; ++nt)
                    MMA_TF32(acc[mt][nt], af[mt], bfr[nt]);
        }
        __syncthreads();
    }

    const int col0 = wn * 48 + (lane & 3) * 2;
    float* ob = out + (size_t)bb * CHW;
#pragma unroll
    for (int mt = 0; mt < 2; ++mt)
#pragma unroll
        for (int hf = 0; hf < 2; ++hf) {
            int rem = rem0 + wm * 32 + mt * 16 + hf * 8 + (lane >> 2);
#pragma unroll
            for (int nt = 0; nt < 6; ++nt) {
#pragma unroll
                for (int j = 0; j < 2; ++j) {
                    int c = col0 + nt * 8 + j;
                    ob[(size_t)c * HW + rem] = acc[mt][nt][hf * 2 + j] + sbias[c];
                }
            }
        }
}

// =====================================================================
// K2: per-window attention, fp16 inputs + m16n8k16 fp16 MMA (f32 accum).
//   smem: q/k double-buffered (2x12544); P fp16 (8KB, aliases buf1);
//   vT fp16 chunk (8KB, aliases buf0); S fp32 at 25088.
// =====================================================================
constexpr int A_QB0 = 0;
constexpr int A_P   = 12544;
constexpr int A_VT  = 0;
constexpr int A_S   = 25088;
constexpr int SMEM_ATTN_BYTES = 25088 + 17408 + 128;   // 42624

__global__ __launch_bounds__(128, 5) void k_attn_mma()
{
    extern __shared__ char smraw[];
    uint32_t sraw = (uint32_t)__cvta_generic_to_shared(smraw);
    const uint32_t s0 = (sraw + 127) & ~127u;
    char* sm = smraw + (s0 - sraw);

    const int tid  = threadIdx.x;
    const int lane = tid & 31, wm = tid >> 5;
    const int lg   = lane >> 3, lr = lane & 7;
    const int win  = blockIdx.x;

    const __half* qg = g_q + (size_t)win * P * Cn;
    const __half* kg = g_k + (size_t)win * P * Cn;
    const __half* vg = g_v + (size_t)win * P * Cn;
    float* sS = (float*)(sm + A_S);

    const int rowA      = wm * 16 + ((lg & 1) << 3) + lr;
    const uint32_t selA = (lg >> 1) << 4;
    const int nrb       = ((lg >> 1) << 3) + lr;
    const uint32_t selB = (lg & 1) << 4;

    // ---- Phase A: S = q k^T  (K=192 fp16, 3 chunks of 64)
    auto prefQK = [&](int kt, int buf) {
        uint32_t qb = s0 + A_QB0 + buf * 12544;
        uint32_t kb = qb + 6272;
        for (int s = tid; s < 392; s += 128) {
            int row = s >> 3, f = s & 7;
            uint32_t o = sw128((uint32_t)(row * 128 + f * 16));
            CP_ASYNC16(qb + o, qg + (size_t)row * Cn + kt * 64 + f * 8);
            CP_ASYNC16(kb + o, kg + (size_t)row * Cn + kt * 64 + f * 8);
        }
    };

    float acc[8][4] = {};
    prefQK(0, 0); CP_COMMIT();
    for (int kt = 0; kt < 3; ++kt) {
        const int cur = kt & 1;
        if (kt < 2) { prefQK(kt + 1, cur ^ 1); CP_COMMIT(); CP_WAIT1(); }
        else        { CP_WAIT0(); }
        __syncthreads();
        const uint32_t qb = s0 + A_QB0 + cur * 12544;
        const uint32_t kb = qb + 6272;
#pragma unroll
        for (int x = 0; x < 4; ++x) {
            uint32_t af[4];
            LDSM4(af[0], af[1], af[2], af[3],
                  qb + sw128((uint32_t)(rowA * 128 + x * 32) + selA));
            uint32_t bfr[8][2];
#pragma unroll
            for (int np = 0; np < 4; ++np) {
                int nr = np * 16 + nrb;
                LDSM4(bfr[2 * np][0], bfr[2 * np][1], bfr[2 * np + 1][0], bfr[2 * np + 1][1],
                      kb + sw128((uint32_t)(nr * 128 + x * 32) + selB));
            }
#pragma unroll
            for (int nt = 0; nt < 8; ++nt)
                MMA_F16(acc[nt], af, bfr[nt]);
        }
        __syncthreads();
    }

    // write scaled S (fp32)
    const float sc = 0.07216878364870323f;     // 1/sqrt(192)
    {
        int rb = wm * 16 + (lane >> 2);
        int cb = (lane & 3) * 2;
#pragma unroll
        for (int hf = 0; hf < 2; ++hf) {
            int i = rb + hf * 8;
#pragma unroll
            for (int nt = 0; nt < 8; ++nt) {
                float2 v;
                v.x = acc[nt][hf * 2 + 0] * sc;
                v.y = acc[nt][hf * 2 + 1] * sc;
                *(float2*)(sS + i * 68 + nt * 8 + cb) = v;
            }
        }
    }
    __syncthreads();

    // softmax (2 threads/row, full-warp shfl); probs -> fp16 P buffer
    {
        const int row = tid >> 1, half = tid & 1;
        const bool valid = (row < P);
        float* r = sS + row * 68;
        char* pP = sm + A_P;
        float mx = -1e30f;
        if (valid)
            for (int j = half; j < P; j += 2) mx = fmaxf(mx, r[j]);
        mx = fmaxf(mx, __shfl_xor_sync(0xFFFFFFFFu, mx, 1));
        float sum = 0.f;
        float ev[25];
        int cnt = 0;
        if (valid)
            for (int j = half; j < P; j += 2) { float e = __expf(r[j] - mx); ev[cnt++] = e; sum += e; }
        sum += __shfl_xor_sync(0xFFFFFFFFu, sum, 1);
        if (valid) {
            float inv = 1.f / sum;
            cnt = 0;
            for (int j = half; j < P; j += 2)
                *(__half*)(pP + sw128((uint32_t)(row * 128 + j * 2))) =
                    __float2half_rn(ev[cnt++] * inv);
            for (int j = P + half; j < 64; j += 2)
                *(__half*)(pP + sw128((uint32_t)(row * 128 + j * 2))) = __float2half_rn(0.f);
        }
    }
    // zero vT pad k-columns (j=50..63) once; j=49 pad handled in fill
    {
        const __half2 z = __floats2half2_rn(0.f, 0.f);
        for (int s = tid; s < 448; s += 128) {
            int c = s / 7, jj = 50 + (s - (s / 7) * 7) * 2;
            *(__half2*)(sm + A_VT + sw128((uint32_t)(c * 128 + jj * 2))) = z;
        }
    }
    __syncthreads();

    // ---- Phase B: O = P @ V, 3 chunks of 64 channels (fp16 MMA, K=64)
    const int bbw = win >> 10, wh = (win >> 5) & 31, ww = win & 31;
    for (int cc = 0; cc < 3; ++cc) {
        if (cc > 0) __syncthreads();
        const int c0 = cc * 64;
        // transpose-fill vT[c][j] fp16 (j pairs; j=49 zero-padded)
        for (int s = tid; s < 200; s += 128) {
            int jp = s >> 3, cg = s & 7;
            int j0 = jp * 2;
            uint4 va = *(const uint4*)(vg + (size_t)j0 * Cn + c0 + cg * 8);
            uint4 vb = make_uint4(0u, 0u, 0u, 0u);
            if (j0 + 1 < P)
                vb = *(const uint4*)(vg + (size_t)(j0 + 1) * Cn + c0 + cg * 8);
            uint32_t ca[4] = {va.x, va.y, va.z, va.w};
            uint32_t cbu[4] = {vb.x, vb.y, vb.z, vb.w};
#pragma unroll
            for (int q = 0; q < 4; ++q) {
                __half2 ha = *(__half2*)&ca[q];
                __half2 hb = *(__half2*)&cbu[q];
                int c = cg * 8 + q * 2;
                *(__half2*)(sm + A_VT + sw128((uint32_t)(c * 128 + jp * 4)))       = __lows2half2(ha, hb);
                *(__half2*)(sm + A_VT + sw128((uint32_t)((c + 1) * 128 + jp * 4))) = __highs2half2(ha, hb);
            }
        }
        __syncthreads();

        float acc2[8][4] = {};
#pragma unroll
        for (int x = 0; x < 4; ++x) {
            uint32_t af[4];
            LDSM4(af[0], af[1], af[2], af[3],
                  s0 + A_P + sw128((uint32_t)(rowA * 128 + x * 32) + selA));
            uint32_t bfr[8][2];
#pragma unroll
            for (int np = 0; np < 4; ++np) {
                int nr = np * 16 + nrb;
                LDSM4(bfr[2 * np][0], bfr[2 * np][1], bfr[2 * np + 1][0], bfr[2 * np + 1][1],
                      s0 + A_VT + sw128((uint32_t)(nr * 128 + x * 32) + selB));
            }
#pragma unroll
            for (int nt = 0; nt < 8; ++nt)
                MMA_F16(acc2[nt], af, bfr[nt]);
        }

        // store O chunk (tf32-rounded fp32) to g_ow pixel-linear
        int rb = wm * 16 + (lane >> 2);
        int cb = (lane & 3) * 2;
#pragma unroll
        for (int hf = 0; hf < 2; ++hf) {
            int i = rb + hf * 8;
            if (i < P) {
                int ph = i / WSz, pw = i - ph * WSz;
                int m = bbw * HW + (wh * WSz + ph) * Wn + ww * WSz + pw;
                float* op = g_ow + (size_t)m * Cn + c0 + cb;
#pragma unroll
                for (int nt = 0; nt < 8; ++nt) {
                    float2 v;
                    v.x = __uint_as_float(f2tf(acc2[nt][hf * 2 + 0]));
                    v.y = __uint_as_float(f2tf(acc2[nt][hf * 2 + 1]));
                    *(float2*)(op + nt * 8) = v;
                }
            }
        }
    }
}

// =====================================================================
extern "C" void kernel_launch(void* const* d_in, const int* in_sizes, int n_in,
                              void* d_out, int out_size)
{
    const float* x  = (const float*)d_in[0];
    const float* Wq = (const float*)d_in[1];
    const float* bq = (const float*)d_in[2];
    const float* Wk = (const float*)d_in[3];
    const float* bk = (const float*)d_in[4];
    const float* Wv = (const float*)d_in[5];
    const float* bv = (const float*)d_in[6];
    const float* Wo = (const float*)d_in[7];
    const float* bo = (const float*)d_in[8];
    float* out = (float*)d_out;

    cudaFuncSetAttribute(k_qkv3,      cudaFuncAttributeMaxDynamicSharedMemorySize, SMEM_QKV_BYTES);
    cudaFuncSetAttribute(k_oproj_mma, cudaFuncAttributeMaxDynamicSharedMemorySize, SMEM_GEMM_BYTES);
    cudaFuncSetAttribute(k_attn_mma,  cudaFuncAttributeMaxDynamicSharedMemorySize, SMEM_ATTN_BYTES);

    k_prep_w<<<(4 * Cn * Cn) / 256, 256>>>(Wq, Wk, Wv, Wo);

    k_qkv3<<<MT / 64, 256, SMEM_QKV_BYTES>>>(x, bq, bk, bv);

    k_attn_mma<<<NWIN, 128, SMEM_ATTN_BYTES>>>();

    k_oproj_mma<<<MT / 64, 256, SMEM_GEMM_BYTES>>>(bo, out);
}

// round 11
// speedup vs baseline: 5.1685x; 1.4562x over previous
#include <cuda_runtime.h>
#include <cuda_fp16.h>
#include <cstdint>

// ---------------- problem constants ----------------
constexpr int Bn  = 8;
constexpr int Cn  = 192;
constexpr int Hn  = 224;
constexpr int Wn  = 224;
constexpr int WSz = 7;
constexpr int HW  = Hn * Wn;          // 50176
constexpr int CHW = Cn * HW;
constexpr int NH  = Hn / WSz;         // 32
constexpr int NWb = NH * NH;          // 1024
constexpr int NWIN = Bn * NWb;        // 8192
constexpr int P   = WSz * WSz;        // 49
constexpr int MT  = Bn * HW;          // 401408

// ---------------- scratch ----------------
__device__ __align__(16) __half g_q [(size_t)NWIN * P * Cn];
__device__ __align__(16) __half g_k [(size_t)NWIN * P * Cn];
__device__ __align__(16) __half g_v [(size_t)NWIN * P * Cn];
__device__ __align__(16) __half g_ow[(size_t)MT * Cn];
__device__ __align__(16) __half g_whf[4][Cn * Cn];    // fp16 weights

// ---------------- helpers ----------------
__device__ __forceinline__ uint32_t sw128(uint32_t o) { return o ^ ((o >> 3) & 0x70); }

#define LDSM4(d0, d1, d2, d3, a) \
    asm volatile("ldmatrix.sync.aligned.m8n8.x4.shared.b16 {%0,%1,%2,%3},[%4];" \
        : "=r"(d0), "=r"(d1), "=r"(d2), "=r"(d3) : "r"(a))

#define MMA_F16(c, a, b) \
    asm volatile("mma.sync.aligned.m16n8k16.row.col.f32.f16.f16.f32 " \
        "{%0,%1,%2,%3},{%4,%5,%6,%7},{%8,%9},{%0,%1,%2,%3};" \
        : "+f"((c)[0]), "+f"((c)[1]), "+f"((c)[2]), "+f"((c)[3]) \
        : "r"((a)[0]), "r"((a)[1]), "r"((a)[2]), "r"((a)[3]), \
          "r"((b)[0]), "r"((b)[1]))

#define CP_ASYNC16(dst, src) \
    asm volatile("cp.async.ca.shared.global [%0],[%1],16;" :: "r"(dst), "l"(src))
#define CP_COMMIT()  asm volatile("cp.async.commit_group;" ::: "memory")
#define CP_WAIT1()   asm volatile("cp.async.wait_group 1;" ::: "memory")
#define CP_WAIT0()   asm volatile("cp.async.wait_group 0;" ::: "memory")

// =====================================================================
// prepass: weights -> fp16 once (tiny)
// =====================================================================
__global__ void k_prep_w(const float* __restrict__ Wq, const float* __restrict__ Wk,
                         const float* __restrict__ Wv, const float* __restrict__ Wo)
{
    int idx = blockIdx.x * 256 + threadIdx.x;
    int wsel = idx / (Cn * Cn);
    int r    = idx - wsel * (Cn * Cn);
    const float* W = (wsel == 0) ? Wq : (wsel == 1) ? Wk : (wsel == 2) ? Wv : Wo;
    g_whf[wsel][r] = __float2half_rn(W[r]);
}

// =====================================================================
// K1: single-pass fused QKV GEMM, all fp16 (m16n8k16, f32 accum).
//   A tile [64 px][192 k] fp16 resident (3 chunks x 8KB), staged from x
//   with pipelining; B fp16 double-buffered. 3 sequential GEMMs.
//   grid = MT/64, block 256 (8 warps, 2m x 4n; warp tile 32x48).
// =====================================================================
constexpr int Q3_A   = 0;          // 3 x 8192 = 24576
constexpr int Q3_B   = 24576;      // 2 x 24576 -> 73728
constexpr int Q3_BI  = 73728;      // 576 floats
constexpr int SMEM_QKV_BYTES = 73728 + 2304 + 128;

__global__ __launch_bounds__(256, 2) void k_qkv3(
    const float* __restrict__ x,
    const float* __restrict__ bq, const float* __restrict__ bk,
    const float* __restrict__ bv)
{
    extern __shared__ char smraw[];
    uint32_t sraw = (uint32_t)__cvta_generic_to_shared(smraw);
    const uint32_t s0 = (sraw + 127) & ~127u;
    char* sm = smraw + (s0 - sraw);
    float* sbias = (float*)(sm + Q3_BI);

    const int tid  = threadIdx.x;
    const int lane = tid & 31, wid = tid >> 5;
    const int wm   = wid >> 2, wn = wid & 3;
    const int m0   = blockIdx.x * 64;
    const int bb   = m0 / HW, rem0 = m0 - bb * HW;
    const float* xb = x + (size_t)bb * CHW + rem0;

    if (tid < 192) {
        sbias[tid]       = bq[tid];
        sbias[192 + tid] = bk[tid];
        sbias[384 + tid] = bv[tid];
    }

    const int lg = lane >> 3, lr = lane & 7;

    // ldmatrix offsets (byte-identical formulas to tf32 version; 32B = K16)
    uint32_t offA[2][4], offB[3][4];
#pragma unroll
    for (int mt = 0; mt < 2; ++mt) {
        int row = wm * 32 + mt * 16 + ((lg & 1) << 3) + lr;
#pragma unroll
        for (int k8 = 0; k8 < 4; ++k8)
            offA[mt][k8] = sw128((uint32_t)(row * 128 + k8 * 32 + ((lg >> 1) << 4)));
    }
#pragma unroll
    for (int np = 0; np < 3; ++np) {
        int nr = wn * 48 + np * 16 + ((lg >> 1) << 3) + lr;
#pragma unroll
        for (int k8 = 0; k8 < 4; ++k8)
            offB[np][k8] = sw128((uint32_t)(nr * 128 + k8 * 32 + ((lg & 1) << 4)));
    }

    int scat[2][2];
#pragma unroll
    for (int mt = 0; mt < 2; ++mt)
#pragma unroll
        for (int hf = 0; hf < 2; ++hf) {
            int rem = rem0 + wm * 32 + mt * 16 + hf * 8 + (lane >> 2);
            int h = rem / Wn, w = rem - h * Wn;
            int hb = h / WSz, wb = w / WSz;
            int win = bb * NWb + hb * NH + wb;
            int pp  = (h - hb * WSz) * WSz + (w - wb * WSz);
            scat[mt][hf] = win * P + pp;
        }

    // ---- A staging: per chunk each thread loads 16 x-floats -> 16 halves
    const int arow = tid & 63;
    const int aseg = tid >> 6;           // 0..3, 16 k each
    float areg[16];

    auto ldA = [&](int c) {
        const float* s = xb + (size_t)(c * 64 + aseg * 16) * HW + arow;
#pragma unroll
        for (int j = 0; j < 16; ++j) areg[j] = s[(size_t)j * HW];
    };
    auto stA = [&](int c) {
        char* ab = sm + Q3_A + c * 8192;
        uint32_t h[8];
#pragma unroll
        for (int q = 0; q < 8; ++q) {
            __half2 p = __floats2half2_rn(areg[2 * q], areg[2 * q + 1]);
            h[q] = *(uint32_t*)&p;
        }
        uint4 u0 = make_uint4(h[0], h[1], h[2], h[3]);
        uint4 u1 = make_uint4(h[4], h[5], h[6], h[7]);
        *(uint4*)(ab + sw128((uint32_t)(arow * 128 + aseg * 32)))      = u0;
        *(uint4*)(ab + sw128((uint32_t)(arow * 128 + aseg * 32 + 16))) = u1;
    };

    auto prefB = [&](int t) {            // t = wsel*3 + kt
        const __half* wsrc = g_whf[t / 3] + (t % 3) * 64;
        uint32_t bbf = s0 + Q3_B + (t & 1) * 24576;
#pragma unroll
        for (int i = 0; i < 6; ++i) {
            int ss = tid + i * 256;
            int bn = ss >> 3, bf = ss & 7;
            CP_ASYNC16(bbf + sw128((uint32_t)(bn * 128 + bf * 16)),
                       wsrc + (size_t)bn * Cn + bf * 8);
        }
    };

    float acc[2][6][4] = {};

    auto gemm_step = [&](uint32_t abase, uint32_t bbase) {
#pragma unroll
        for (int k8 = 0; k8 < 4; ++k8) {
            uint32_t af[2][4];
#pragma unroll
            for (int mt = 0; mt < 2; ++mt)
                LDSM4(af[mt][0], af[mt][1], af[mt][2], af[mt][3], abase + offA[mt][k8]);
            uint32_t bfr[6][2];
#pragma unroll
            for (int np = 0; np < 3; ++np)
                LDSM4(bfr[2 * np][0], bfr[2 * np][1], bfr[2 * np + 1][0], bfr[2 * np + 1][1],
                      bbase + offB[np][k8]);
#pragma unroll
            for (int mt = 0; mt < 2; ++mt)
#pragma unroll
                for (int nt = 0; nt < 6; ++nt)
                    MMA_F16(acc[mt][nt], af[mt], bfr[nt]);
        }
    };

    __half* dsts[3] = {g_q, g_k, g_v};
    auto do_epi = [&](int w) {
        __half* dst = dsts[w];
        const float* bofs = sbias + w * 192;
        const int col0 = wn * 48 + (lane & 3) * 2;
#pragma unroll
        for (int mt = 0; mt < 2; ++mt)
#pragma unroll
            for (int hf = 0; hf < 2; ++hf) {
                __half* dp = dst + (size_t)scat[mt][hf] * Cn;
#pragma unroll
                for (int nt = 0; nt < 6; ++nt) {
                    int c = col0 + nt * 8;
                    *(__half2*)(dp + c) = __floats2half2_rn(
                        acc[mt][nt][hf * 2 + 0] + bofs[c],
                        acc[mt][nt][hf * 2 + 1] + bofs[c + 1]);
                    acc[mt][nt][hf * 2 + 0] = 0.f;
                    acc[mt][nt][hf * 2 + 1] = 0.f;
                }
            }
    };

    // prologue: chunk 0 staged; chunk-1 LDGs in flight; B(0) queued
    ldA(0);
    prefB(0); CP_COMMIT();
    stA(0);
    ldA(1);
    __syncthreads();

    // t = wsel*3 + kt, t = 0..8
#pragma unroll 3
    for (int t = 0; t < 9; ++t) {
        if (t < 8) { prefB(t + 1); CP_COMMIT(); CP_WAIT1(); }
        else       { CP_WAIT0(); }
        __syncthreads();
        if (t == 0) { stA(1); ldA(2); }
        if (t == 1) { stA(2); }
        gemm_step(s0 + Q3_A + (t - (t / 3) * 3) * 8192,
                  s0 + Q3_B + (t & 1) * 24576);
        __syncthreads();
        if (t == 2) do_epi(0);
        if (t == 5) do_epi(1);
    }
    do_epi(2);
}

// =====================================================================
// K3: output projection GEMM, all fp16 (A = g_ow fp16, B = Wo fp16).
//   3 K-chunks of 64; A+B double-buffered. out fp32.
// =====================================================================
constexpr int GOFF_A  = 0;          // 2 x 8192
constexpr int GOFF_B  = 16384;      // 2 x 24576 -> 65536
constexpr int GOFF_BI = 65536;
constexpr int SMEM_GEMM_BYTES = 65536 + 768 + 128;

__global__ __launch_bounds__(256, 2) void k_oproj_mma(
    const float* __restrict__ bo, float* __restrict__ out)
{
    extern __shared__ char smraw[];
    uint32_t sraw = (uint32_t)__cvta_generic_to_shared(smraw);
    const uint32_t s0 = (sraw + 127) & ~127u;
    char* sm = smraw + (s0 - sraw);
    float* sbias = (float*)(sm + GOFF_BI);

    const int tid  = threadIdx.x;
    const int lane = tid & 31, wid = tid >> 5;
    const int wm   = wid >> 2, wn = wid & 3;
    const int m0   = blockIdx.x * 64;
    const int bb   = m0 / HW, rem0 = m0 - bb * HW;
    const __half* Wt = g_whf[3];

    if (tid < 192) sbias[tid] = bo[tid];

    const int lg = lane >> 3, lr = lane & 7;

    uint32_t offA[2][4], offB[3][4];
#pragma unroll
    for (int mt = 0; mt < 2; ++mt) {
        int row = wm * 32 + mt * 16 + ((lg & 1) << 3) + lr;
#pragma unroll
        for (int k8 = 0; k8 < 4; ++k8)
            offA[mt][k8] = sw128((uint32_t)(row * 128 + k8 * 32 + ((lg >> 1) << 4)));
    }
#pragma unroll
    for (int np = 0; np < 3; ++np) {
        int nr = wn * 48 + np * 16 + ((lg >> 1) << 3) + lr;
#pragma unroll
        for (int k8 = 0; k8 < 4; ++k8)
            offB[np][k8] = sw128((uint32_t)(nr * 128 + k8 * 32 + ((lg & 1) << 4)));
    }

    float acc[2][6][4] = {};

    auto prefetch = [&](int kt, int buf) {
        uint32_t ab  = s0 + GOFF_A + buf * 8192;
        uint32_t bbf = s0 + GOFF_B + buf * 24576;
        {   // A: 64 rows x 4 segs of 16B -> exactly 256 slots
            int r = tid >> 2, f = tid & 3;
            CP_ASYNC16(ab + sw128((uint32_t)(r * 128 + f * 32)),
                       g_ow + (size_t)(m0 + r) * Cn + kt * 64 + f * 16);
            CP_ASYNC16(ab + sw128((uint32_t)(r * 128 + f * 32 + 16)),
                       g_ow + (size_t)(m0 + r) * Cn + kt * 64 + f * 16 + 8);
        }
        const __half* wsrc = Wt + kt * 64;
#pragma unroll
        for (int i = 0; i < 6; ++i) {
            int ss = tid + i * 256;
            int bn = ss >> 3, bf = ss & 7;
            CP_ASYNC16(bbf + sw128((uint32_t)(bn * 128 + bf * 16)),
                       wsrc + (size_t)bn * Cn + bf * 8);
        }
    };

    prefetch(0, 0); CP_COMMIT();
    for (int kt = 0; kt < 3; ++kt) {
        const int cur = kt & 1;
        if (kt < 2) { prefetch(kt + 1, cur ^ 1); CP_COMMIT(); CP_WAIT1(); }
        else        { CP_WAIT0(); }
        __syncthreads();
        const uint32_t abase = s0 + GOFF_A + cur * 8192;
        const uint32_t bbase = s0 + GOFF_B + cur * 24576;
#pragma unroll
        for (int k8 = 0; k8 < 4; ++k8) {
            uint32_t af[2][4];
#pragma unroll
            for (int mt = 0; mt < 2; ++mt)
                LDSM4(af[mt][0], af[mt][1], af[mt][2], af[mt][3], abase + offA[mt][k8]);
            uint32_t bfr[6][2];
#pragma unroll
            for (int np = 0; np < 3; ++np)
                LDSM4(bfr[2 * np][0], bfr[2 * np][1], bfr[2 * np + 1][0], bfr[2 * np + 1][1],
                      bbase + offB[np][k8]);
#pragma unroll
            for (int mt = 0; mt < 2; ++mt)
#pragma unroll
                for (int nt = 0; nt < 6; ++nt)
                    MMA_F16(acc[mt][nt], af[mt], bfr[nt]);
        }
        __syncthreads();
    }

    const int col0 = wn * 48 + (lane & 3) * 2;
    float* ob = out + (size_t)bb * CHW;
#pragma unroll
    for (int mt = 0; mt < 2; ++mt)
#pragma unroll
        for (int hf = 0; hf < 2; ++hf) {
            int rem = rem0 + wm * 32 + mt * 16 + hf * 8 + (lane >> 2);
#pragma unroll
            for (int nt = 0; nt < 6; ++nt) {
#pragma unroll
                for (int j = 0; j < 2; ++j) {
                    int c = col0 + nt * 8 + j;
                    ob[(size_t)c * HW + rem] = acc[mt][nt][hf * 2 + j] + sbias[c];
                }
            }
        }
}

// =====================================================================
// K2: per-window attention, fp16 (unchanged from round 10 except
//     g_ow is now fp16: phase-B stores half2 directly).
// =====================================================================
constexpr int A_QB0 = 0;
constexpr int A_P   = 12544;
constexpr int A_VT  = 0;
constexpr int A_S   = 25088;
constexpr int SMEM_ATTN_BYTES = 25088 + 17408 + 128;   // 42624

__global__ __launch_bounds__(128, 5) void k_attn_mma()
{
    extern __shared__ char smraw[];
    uint32_t sraw = (uint32_t)__cvta_generic_to_shared(smraw);
    const uint32_t s0 = (sraw + 127) & ~127u;
    char* sm = smraw + (s0 - sraw);

    const int tid  = threadIdx.x;
    const int lane = tid & 31, wm = tid >> 5;
    const int lg   = lane >> 3, lr = lane & 7;
    const int win  = blockIdx.x;

    const __half* qg = g_q + (size_t)win * P * Cn;
    const __half* kg = g_k + (size_t)win * P * Cn;
    const __half* vg = g_v + (size_t)win * P * Cn;
    float* sS = (float*)(sm + A_S);

    const int rowA      = wm * 16 + ((lg & 1) << 3) + lr;
    const uint32_t selA = (lg >> 1) << 4;
    const int nrb       = ((lg >> 1) << 3) + lr;
    const uint32_t selB = (lg & 1) << 4;

    auto prefQK = [&](int kt, int buf) {
        uint32_t qb = s0 + A_QB0 + buf * 12544;
        uint32_t kb = qb + 6272;
        for (int s = tid; s < 392; s += 128) {
            int row = s >> 3, f = s & 7;
            uint32_t o = sw128((uint32_t)(row * 128 + f * 16));
            CP_ASYNC16(qb + o, qg + (size_t)row * Cn + kt * 64 + f * 8);
            CP_ASYNC16(kb + o, kg + (size_t)row * Cn + kt * 64 + f * 8);
        }
    };

    float acc[8][4] = {};
    prefQK(0, 0); CP_COMMIT();
    for (int kt = 0; kt < 3; ++kt) {
        const int cur = kt & 1;
        if (kt < 2) { prefQK(kt + 1, cur ^ 1); CP_COMMIT(); CP_WAIT1(); }
        else        { CP_WAIT0(); }
        __syncthreads();
        const uint32_t qb = s0 + A_QB0 + cur * 12544;
        const uint32_t kb = qb + 6272;
#pragma unroll
        for (int x = 0; x < 4; ++x) {
            uint32_t af[4];
            LDSM4(af[0], af[1], af[2], af[3],
                  qb + sw128((uint32_t)(rowA * 128 + x * 32) + selA));
            uint32_t bfr[8][2];
#pragma unroll
            for (int np = 0; np < 4; ++np) {
                int nr = np * 16 + nrb;
                LDSM4(bfr[2 * np][0], bfr[2 * np][1], bfr[2 * np + 1][0], bfr[2 * np + 1][1],
                      kb + sw128((uint32_t)(nr * 128 + x * 32) + selB));
            }
#pragma unroll
            for (int nt = 0; nt < 8; ++nt)
                MMA_F16(acc[nt], af, bfr[nt]);
        }
        __syncthreads();
    }

    const float sc = 0.07216878364870323f;     // 1/sqrt(192)
    {
        int rb = wm * 16 + (lane >> 2);
        int cb = (lane & 3) * 2;
#pragma unroll
        for (int hf = 0; hf < 2; ++hf) {
            int i = rb + hf * 8;
#pragma unroll
            for (int nt = 0; nt < 8; ++nt) {
                float2 v;
                v.x = acc[nt][hf * 2 + 0] * sc;
                v.y = acc[nt][hf * 2 + 1] * sc;
                *(float2*)(sS + i * 68 + nt * 8 + cb) = v;
            }
        }
    }
    __syncthreads();

    // softmax (2 threads/row, full-warp shfl); probs -> fp16 P buffer
    {
        const int row = tid >> 1, half = tid & 1;
        const bool valid = (row < P);
        float* r = sS + row * 68;
        char* pP = sm + A_P;
        float mx = -1e30f;
        if (valid)
            for (int j = half; j < P; j += 2) mx = fmaxf(mx, r[j]);
        mx = fmaxf(mx, __shfl_xor_sync(0xFFFFFFFFu, mx, 1));
        float sum = 0.f;
        float ev[25];
        int cnt = 0;
        if (valid)
            for (int j = half; j < P; j += 2) { float e = __expf(r[j] - mx); ev[cnt++] = e; sum += e; }
        sum += __shfl_xor_sync(0xFFFFFFFFu, sum, 1);
        if (valid) {
            float inv = 1.f / sum;
            cnt = 0;
            for (int j = half; j < P; j += 2)
                *(__half*)(pP + sw128((uint32_t)(row * 128 + j * 2))) =
                    __float2half_rn(ev[cnt++] * inv);
            for (int j = P + half; j < 64; j += 2)
                *(__half*)(pP + sw128((uint32_t)(row * 128 + j * 2))) = __float2half_rn(0.f);
        }
    }
    // zero vT pad k-columns (j=50..63) once
    {
        const __half2 z = __floats2half2_rn(0.f, 0.f);
        for (int s = tid; s < 448; s += 128) {
            int c = s / 7, jj = 50 + (s - (s / 7) * 7) * 2;
            *(__half2*)(sm + A_VT + sw128((uint32_t)(c * 128 + jj * 2))) = z;
        }
    }
    __syncthreads();

    // Phase B: O = P @ V, 3 chunks of 64 channels
    const int bbw = win >> 10, wh = (win >> 5) & 31, ww = win & 31;
    for (int cc = 0; cc < 3; ++cc) {
        if (cc > 0) __syncthreads();
        const int c0 = cc * 64;
        for (int s = tid; s < 200; s += 128) {
            int jp = s >> 3, cg = s & 7;
            int j0 = jp * 2;
            uint4 va = *(const uint4*)(vg + (size_t)j0 * Cn + c0 + cg * 8);
            uint4 vb = make_uint4(0u, 0u, 0u, 0u);
            if (j0 + 1 < P)
                vb = *(const uint4*)(vg + (size_t)(j0 + 1) * Cn + c0 + cg * 8);
            uint32_t ca[4] = {va.x, va.y, va.z, va.w};
            uint32_t cbu[4] = {vb.x, vb.y, vb.z, vb.w};
#pragma unroll
            for (int q = 0; q < 4; ++q) {
                __half2 ha = *(__half2*)&ca[q];
                __half2 hb = *(__half2*)&cbu[q];
                int c = cg * 8 + q * 2;
                *(__half2*)(sm + A_VT + sw128((uint32_t)(c * 128 + jp * 4)))       = __lows2half2(ha, hb);
                *(__half2*)(sm + A_VT + sw128((uint32_t)((c + 1) * 128 + jp * 4))) = __highs2half2(ha, hb);
            }
        }
        __syncthreads();

        float acc2[8][4] = {};
#pragma unroll
        for (int x = 0; x < 4; ++x) {
            uint32_t af[4];
            LDSM4(af[0], af[1], af[2], af[3],
                  s0 + A_P + sw128((uint32_t)(rowA * 128 + x * 32) + selA));
            uint32_t bfr[8][2];
#pragma unroll
            for (int np = 0; np < 4; ++np) {
                int nr = np * 16 + nrb;
                LDSM4(bfr[2 * np][0], bfr[2 * np][1], bfr[2 * np + 1][0], bfr[2 * np + 1][1],
                      s0 + A_VT + sw128((uint32_t)(nr * 128 + x * 32) + selB));
            }
#pragma unroll
            for (int nt = 0; nt < 8; ++nt)
                MMA_F16(acc2[nt], af, bfr[nt]);
        }

        int rb = wm * 16 + (lane >> 2);
        int cb = (lane & 3) * 2;
#pragma unroll
        for (int hf = 0; hf < 2; ++hf) {
            int i = rb + hf * 8;
            if (i < P) {
                int ph = i / WSz, pw = i - ph * WSz;
                int m = bbw * HW + (wh * WSz + ph) * Wn + ww * WSz + pw;
                __half* op = g_ow + (size_t)m * Cn + c0 + cb;
#pragma unroll
                for (int nt = 0; nt < 8; ++nt)
                    *(__half2*)(op + nt * 8) = __floats2half2_rn(
                        acc2[nt][hf * 2 + 0], acc2[nt][hf * 2 + 1]);
            }
        }
    }
}

// =====================================================================
extern "C" void kernel_launch(void* const* d_in, const int* in_sizes, int n_in,
                              void* d_out, int out_size)
{
    const float* x  = (const float*)d_in[0];
    const float* Wq = (const float*)d_in[1];
    const float* bq = (const float*)d_in[2];
    const float* Wk = (const float*)d_in[3];
    const float* bk = (const float*)d_in[4];
    const float* Wv = (const float*)d_in[5];
    const float* bv = (const float*)d_in[6];
    const float* Wo = (const float*)d_in[7];
    const float* bo = (const float*)d_in[8];
    float* out = (float*)d_out;

    cudaFuncSetAttribute(k_qkv3,      cudaFuncAttributeMaxDynamicSharedMemorySize, SMEM_QKV_BYTES);
    cudaFuncSetAttribute(k_oproj_mma, cudaFuncAttributeMaxDynamicSharedMemorySize, SMEM_GEMM_BYTES);
    cudaFuncSetAttribute(k_attn_mma,  cudaFuncAttributeMaxDynamicSharedMemorySize, SMEM_ATTN_BYTES);

    k_prep_w<<<(4 * Cn * Cn) / 256, 256>>>(Wq, Wk, Wv, Wo);

    k_qkv3<<<MT / 64, 256, SMEM_QKV_BYTES>>>(x, bq, bk, bv);

    k_attn_mma<<<NWIN, 128, SMEM_ATTN_BYTES>>>();

    k_oproj_mma<<<MT / 64, 256, SMEM_GEMM_BYTES>>>(bo, out);
}